// round 8
// baseline (speedup 1.0000x reference)
#include <cuda_runtime.h>
#include <cstdint>

typedef unsigned long long u64;
typedef unsigned int u32;

// ---------------- problem constants ----------------
#define BB 8
#define CC 256
#define NPOS 21824              // per-image positions across 5 maps
#define NANCH 196416            // NPOS * 9
#define NKEY 196608             // 48 * 4096 (padded)
#define KSEL 300
#define NCHUNK 48               // stage1 chunks of 4096 per image
#define NCAND (NCHUNK * KSEL)   // 14400 candidates per image
#define NLOGIT (BB * NPOS * 9)  // 1571328

__device__ __constant__ int c_mapS[5]   = {128, 64, 32, 16, 8};
__device__ __constant__ int c_mapOff[5] = {0, 16384, 20480, 21504, 21760};

// ---------------- device scratch ----------------
__device__ float g_wT[256 * 9 * 256];            // [ic][tap][oc]
__device__ float g_logits[(size_t)2 * NLOGIT];   // dual-slot (2 atomic adds each -> deterministic)
__device__ u64   g_keys[(size_t)BB * NKEY];
__device__ u64   g_cand[(size_t)BB * NCAND];
__device__ int   g_sel[BB * KSEL];

// ---------------- f32x2 helpers ----------------
__device__ __forceinline__ u64 dup2(float x) {
    u64 r; asm("mov.b64 %0,{%1,%1};" : "=l"(r) : "f"(x)); return r;
}
__device__ __forceinline__ void ffma2(u64 &c, u64 a, u64 b) {
    asm("fma.rn.f32x2 %0,%1,%2,%3;" : "=l"(c) : "l"(a), "l"(b), "l"(c));
}
__device__ __forceinline__ void fadd2(u64 &c, u64 a) {
    asm("add.rn.f32x2 %0,%1,%2;" : "=l"(c) : "l"(c), "l"(a));
}
__device__ __forceinline__ float2 unpack2(u64 v) {
    float2 f; asm("mov.b64 {%0,%1},%2;" : "=f"(f.x), "=f"(f.y) : "l"(v)); return f;
}

// ---------------- kernel 0a: zero logits + key padding (every replay) ----------------
__global__ void k_init() {
    int i = blockIdx.x * 1024 + threadIdx.x;
    if (i < 2 * NLOGIT) g_logits[i] = 0.f;
    if (i < BB * (NKEY - NANCH)) {
        int b = i / (NKEY - NANCH);
        int r = i - b * (NKEY - NANCH);
        g_keys[(size_t)b * NKEY + NANCH + r] = 0ull;
    }
}

// ---------------- kernel 0b: weight transpose [oc][ic][t] -> [ic][t][oc] ----------------
__global__ void k_wtrans(const float* __restrict__ w_pre) {
    int i = blockIdx.x * 1024 + threadIdx.x;
    if (i >= 256 * 9 * 256) return;
    int oc = i & 255;
    int rest = i >> 8;
    int tap = rest % 9;
    int ic = rest / 9;
    g_wT[i] = w_pre[(oc * 256 + ic) * 9 + tap];
}

// ---------------- kernel 1: conv3x3 + bias + relu + fused 1x1 proj ----------------
// Merged over all 5 maps. Block: 8x8 tile x 64 oc (z quarter). 256 threads.
// Thread: 2x2 pixels x 4 oc (2 f32x2 oc-pair regs). cp.async double-buffered.
// Quarter-oc blocks halve T_blk (tail shrink); per-output accumulation chains
// are bitwise identical (ic 0..7, dy, dx per chunk, 32 chunk folds).
// Proj epilogue: og-tree (fixed order) -> quarter partial; quarters {0,1} atomic
// into logits slot0, {2,3} into slot1 (2 commutative adds per slot = deterministic).

#define IB_FLOATS 960            // 8*10*12
#define WBQ_FLOATS 4608          // 8*9*64 (quarter)
#define W_CHUNK_BYTES 73728      // 8*9*256*4 (full g_wT chunk stride)

#define LOADROW(dst, rr) { \
    float2 a_ = *(const float2*)(ib + (rr)*12); \
    float2 b_ = *(const float2*)(ib + (rr)*12 + 2); \
    dst[0] = dup2(a_.x); dst[1] = dup2(a_.y); \
    dst[2] = dup2(b_.x); dst[3] = dup2(b_.y); }

#define TAPROW(dy, top, bot) { \
    _Pragma("unroll") \
    for (int dx = 0; dx < 3; ++dx) { \
        ulonglong2 wA = *(const ulonglong2*)(wb + ((dy)*3 + dx) * 64); \
        ffma2(ch[0][0], top[dx],   wA.x); ffma2(ch[0][1], top[dx],   wA.y); \
        ffma2(ch[1][0], top[dx+1], wA.x); ffma2(ch[1][1], top[dx+1], wA.y); \
        ffma2(ch[2][0], bot[dx],   wA.x); ffma2(ch[2][1], bot[dx],   wA.y); \
        ffma2(ch[3][0], bot[dx+1], wA.x); ffma2(ch[3][1], bot[dx+1], wA.y); \
    } }

__global__ void __launch_bounds__(256, 2)
k_conv(const float* __restrict__ fm0, const float* __restrict__ fm1,
       const float* __restrict__ fm2, const float* __restrict__ fm3,
       const float* __restrict__ fm4, const float* __restrict__ b_pre,
       const float* __restrict__ w_proj) {
    extern __shared__ float sm[];
    float* ibuf[2] = {sm, sm + IB_FLOATS};
    float* wbuf[2] = {sm + 2 * IB_FLOATS, sm + 2 * IB_FLOATS + WBQ_FLOATS};
    const u32 smb = (u32)__cvta_generic_to_shared(sm);
    const u32 ibs[2] = {smb, smb + IB_FLOATS * 4};
    const u32 wbs[2] = {smb + 2 * IB_FLOATS * 4, smb + 2 * IB_FLOATS * 4 + WBQ_FLOATS * 4};

    const int tid = threadIdx.x;
    const int b = blockIdx.y;
    const int zq = blockIdx.z;            // oc quarter: 0..3

    // map lookup
    int bx = blockIdx.x, m, tile;
    if (bx < 256)      { m = 0; tile = bx; }
    else if (bx < 320) { m = 1; tile = bx - 256; }
    else if (bx < 336) { m = 2; tile = bx - 320; }
    else if (bx < 340) { m = 3; tile = bx - 336; }
    else               { m = 4; tile = bx - 340; }
    const int s = c_mapS[m];
    const int HW = s * s;
    const int posOff = c_mapOff[m];
    const float* fm = (m == 0) ? fm0 : (m == 1) ? fm1 : (m == 2) ? fm2 : (m == 3) ? fm3 : fm4;

    const int tilesX = s >> 3;
    const int ty0 = (tile / tilesX) << 3;
    const int tx0 = (tile % tilesX) << 3;

    const int pg = tid & 15;
    const int og = tid >> 4;              // 0..15 -> oc = zq*64 + og*4 + ..
    const int py = (pg >> 2) << 1;
    const int px = (pg & 3) << 1;

    const char* fb = (const char*)(fm + (size_t)b * 256 * HW);

    // ---- precompute cp.async descriptors (loop-invariant) ----
    bool in_act[4];
    u32  in_so[4], in_go[4], in_sz[4];
#pragma unroll
    for (int k = 0; k < 4; ++k) {
        int idx = tid + (k << 8);
        in_act[k] = (idx < 800);
        int ii = in_act[k] ? idx : 0;
        int ic = ii / 100;
        int rem = ii - ic * 100;
        int r = rem / 10;
        int c = rem - 10 * r;
        int gy = ty0 - 1 + r, gx = tx0 - 1 + c;
        bool ok = (gy >= 0) && (gy < s) && (gx >= 0) && (gx < s);
        in_so[k] = (u32)(((ic * 10 + r) * 12 + c) * 4);
        in_go[k] = ok ? (u32)((ic * HW + gy * s + gx) * 4) : 0u;
        in_sz[k] = ok ? 4u : 0u;
    }
    // weights: 1152 float4 per chunk (quarter) -> thread handles i = tid + k*256, k=0..4
    bool w_act[5];
    u32 w_so[5], w_go[5];
#pragma unroll
    for (int k = 0; k < 5; ++k) {
        int i = tid + (k << 8);
        w_act[k] = (i < 1152);
        int ii = w_act[k] ? i : 0;
        int icL = ii / 144;
        int rem = ii - icL * 144;
        int tap = rem >> 4;
        int q = rem & 15;
        w_so[k] = (u32)(ii * 16);
        w_go[k] = (u32)((((icL * 9 + tap) << 6) + (zq << 4) + q) * 16);
    }
    const char* wtb = (const char*)g_wT;

    u64 acc[4][2];
#pragma unroll
    for (int p = 0; p < 4; ++p)
#pragma unroll
        for (int j = 0; j < 2; ++j) acc[p][j] = 0ull;

    // issue chunk 0
    {
#pragma unroll
        for (int k = 0; k < 4; ++k) if (in_act[k])
            asm volatile("cp.async.ca.shared.global [%0], [%1], 4, %2;"
                         :: "r"(ibs[0] + in_so[k]), "l"(fb + in_go[k]), "r"(in_sz[k]) : "memory");
#pragma unroll
        for (int k = 0; k < 5; ++k) if (w_act[k])
            asm volatile("cp.async.cg.shared.global [%0], [%1], 16;"
                         :: "r"(wbs[0] + w_so[k]), "l"(wtb + w_go[k]) : "memory");
        asm volatile("cp.async.commit_group;" ::: "memory");
    }

    const u32 inStride = (u32)(8 * HW * 4);

    for (int cc = 0; cc < 32; ++cc) {
        const int cur = cc & 1;
        asm volatile("cp.async.wait_group 0;" ::: "memory");
        __syncthreads();
        if (cc < 31) {
            const char* f = fb + (size_t)(cc + 1) * inStride;
            const char* w = wtb + (size_t)(cc + 1) * W_CHUNK_BYTES;
            const u32 ibS = ibs[cur ^ 1], wbS = wbs[cur ^ 1];
#pragma unroll
            for (int k = 0; k < 4; ++k) if (in_act[k])
                asm volatile("cp.async.ca.shared.global [%0], [%1], 4, %2;"
                             :: "r"(ibS + in_so[k]), "l"(f + in_go[k]), "r"(in_sz[k]) : "memory");
#pragma unroll
            for (int k = 0; k < 5; ++k) if (w_act[k])
                asm volatile("cp.async.cg.shared.global [%0], [%1], 16;"
                             :: "r"(wbS + w_so[k]), "l"(w + w_go[k]) : "memory");
            asm volatile("cp.async.commit_group;" ::: "memory");
        }

        u64 ch[4][2];
#pragma unroll
        for (int p = 0; p < 4; ++p)
#pragma unroll
            for (int j = 0; j < 2; ++j) ch[p][j] = 0ull;

        const float* ibase = ibuf[cur] + py * 12 + px;
        const float* wbase2 = wbuf[cur] + og * 4;
#pragma unroll
        for (int ic = 0; ic < 8; ++ic) {
            const float* ib = ibase + ic * 120;
            const float* wb = wbase2 + ic * 576;
            u64 rA[4], rB[4];
            LOADROW(rA, 0);
            LOADROW(rB, 1);
            TAPROW(0, rA, rB);
            LOADROW(rA, 2);
            TAPROW(1, rB, rA);
            LOADROW(rB, 3);
            TAPROW(2, rA, rB);
        }
#pragma unroll
        for (int p = 0; p < 4; ++p)
#pragma unroll
            for (int j = 0; j < 2; ++j) fadd2(acc[p][j], ch[p][j]);
    }

    // all warps done reading weight buffers before reusing them as reduction space
    __syncthreads();

    // ---- fused epilogue: bias + relu + 1x1 proj partials ----
    float part[4][9];
#pragma unroll
    for (int p = 0; p < 4; ++p)
#pragma unroll
        for (int a = 0; a < 9; ++a) part[p][a] = 0.f;

#pragma unroll
    for (int j = 0; j < 2; ++j) {
        const int oc = zq * 64 + og * 4 + 2 * j;
        const float b0 = b_pre[oc], b1 = b_pre[oc + 1];
#pragma unroll
        for (int p = 0; p < 4; ++p) {
            float2 v = unpack2(acc[p][j]);
            float r0 = fmaxf(v.x + b0, 0.f);
            float r1 = fmaxf(v.y + b1, 0.f);
#pragma unroll
            for (int a = 0; a < 9; ++a) {
                float t = part[p][a];
                t = fmaf(r0, w_proj[a * 256 + oc], t);
                t = fmaf(r1, w_proj[a * 256 + oc + 1], t);
                part[p][a] = t;
            }
        }
    }

    // stage partials: [og(16)][pixel(64)][anchor(9)] over the (now free) weight buffers
    float* red = sm + 2 * IB_FLOATS;   // 9216 floats = both weight buffers
#pragma unroll
    for (int p = 0; p < 4; ++p) {
        int pl = (py + (p >> 1)) * 8 + (px + (p & 1));
#pragma unroll
        for (int a = 0; a < 9; ++a)
            red[(og * 64 + pl) * 9 + a] = part[p][a];
    }
    __syncthreads();

    // reduce over og in fixed ascending order -> dual-slot atomicAdd
    float* lslot = g_logits + (size_t)(zq >> 1) * NLOGIT;
    for (int item = tid; item < 576; item += 256) {
        int pl = item / 9;
        int a = item - 9 * pl;
        float v = 0.f;
#pragma unroll
        for (int o = 0; o < 16; ++o)
            v += red[(o * 64 + pl) * 9 + a];
        int gy = ty0 + (pl >> 3);
        int gx = tx0 + (pl & 7);
        int pos = posOff + gy * s + gx;
        atomicAdd(&lslot[((size_t)b * NPOS + pos) * 9 + a], v);
    }
}

// ---------------- kernel 2: logits -> sigmoid -> sortable keys ----------------
__global__ void __launch_bounds__(256)
k_keys(const float* __restrict__ b_proj) {
    int gid = blockIdx.x * 256 + threadIdx.x;
    if (gid >= BB * NPOS) return;
    int b = gid / NPOS;
    int p = gid - b * NPOS;
    const float* lg0 = g_logits + (size_t)gid * 9;
    const float* lg1 = g_logits + (size_t)NLOGIT + (size_t)gid * 9;
    u64* kb = g_keys + (size_t)b * NKEY + (size_t)p * 9;
#pragma unroll
    for (int a = 0; a < 9; ++a) {
        float logit = (lg0[a] + lg1[a]) + b_proj[a];
        float prob = 1.0f / (1.0f + expf(-logit));
        u32 pb = __float_as_uint(prob);                 // prob>0 => bit-monotonic
        u32 idx = (u32)(p * 9 + a);
        kb[a] = ((u64)pb << 32) | (u64)(0xFFFFFFFFu - idx);  // tie -> lower idx first
    }
}

// ---------------- bitonic helpers (descending) ----------------
__device__ __forceinline__ void bitonic_step(u64* sk, int i, int j, int k) {
    int ixj = i | j;
    u64 a = sk[i], b = sk[ixj];
    bool dir = ((i & k) == 0);
    bool sw = dir ? (a < b) : (a > b);
    if (sw) { sk[i] = b; sk[ixj] = a; }
}

// ---------------- kernel 3: stage1 — sort each 4096 chunk, keep top 300 ----------------
__global__ void __launch_bounds__(512)
k_top1() {
    __shared__ u64 sk[4096];
    const int tid = threadIdx.x;
    const int blk = blockIdx.x;
    const int b = blockIdx.y;
    const u64* src = g_keys + (size_t)b * NKEY + (size_t)blk * 4096;
    for (int i = tid; i < 4096; i += 512) sk[i] = src[i];
    for (int k = 2; k <= 4096; k <<= 1) {
        for (int j = k >> 1; j > 0; j >>= 1) {
            __syncthreads();
            for (int t = tid; t < 2048; t += 512) {
                int i = ((t & ~(j - 1)) << 1) | (t & (j - 1));
                bitonic_step(sk, i, j, k);
            }
        }
    }
    __syncthreads();
    u64* dst = g_cand + ((size_t)b * NCHUNK + blk) * KSEL;
    for (int i = tid; i < KSEL; i += 512) dst[i] = sk[i];
}

// ---------------- kernel 4: stage2 — merge 14400 candidates per image ----------------
__global__ void __launch_bounds__(1024)
k_top2() {
    extern __shared__ u64 sk2[];   // 16384 keys = 128KB
    const int tid = threadIdx.x;
    const int b = blockIdx.x;
    const u64* src = g_cand + (size_t)b * NCAND;
    for (int i = tid; i < 16384; i += 1024) sk2[i] = (i < NCAND) ? src[i] : 0ull;
    for (int k = 2; k <= 16384; k <<= 1) {
        for (int j = k >> 1; j > 0; j >>= 1) {
            __syncthreads();
            for (int t = tid; t < 8192; t += 1024) {
                int i = ((t & ~(j - 1)) << 1) | (t & (j - 1));
                bitonic_step(sk2, i, j, k);
            }
        }
    }
    __syncthreads();
    if (tid < KSEL)
        g_sel[b * KSEL + tid] = (int)(0xFFFFFFFFu - (u32)(sk2[tid] & 0xFFFFFFFFull));
}

// ---------------- kernel 5: gather features + per-anchor 256x256 matvec ----------------
__global__ void __launch_bounds__(256)
k_post(const float* __restrict__ fm0, const float* __restrict__ fm1,
       const float* __restrict__ fm2, const float* __restrict__ fm3,
       const float* __restrict__ fm4, const float* __restrict__ w_post,
       const float* __restrict__ b_post, float* __restrict__ out) {
    __shared__ float x[256];
    const int n = blockIdx.x;
    const int tid = threadIdx.x;
    const int b = n / KSEL;
    const int anchor = g_sel[n];
    const int pos = anchor / 9;
    const int a = anchor - 9 * (anchor / 9);

    int m, hw, HW;
    if (pos < 16384)      { m = 0; hw = pos;         HW = 16384; }
    else if (pos < 20480) { m = 1; hw = pos - 16384; HW = 4096;  }
    else if (pos < 21504) { m = 2; hw = pos - 20480; HW = 1024;  }
    else if (pos < 21760) { m = 3; hw = pos - 21504; HW = 256;   }
    else                  { m = 4; hw = pos - 21760; HW = 64;    }
    const float* fm = (m == 0) ? fm0 : (m == 1) ? fm1 : (m == 2) ? fm2 : (m == 3) ? fm3 : fm4;

    x[tid] = fm[((size_t)b * 256 + tid) * HW + hw];
    __syncthreads();

    const float* W = w_post + (size_t)a * 65536;
    float accv = b_post[a * 256 + tid];
#pragma unroll 8
    for (int d = 0; d < 256; ++d)
        accv += x[d] * W[d * 256 + tid];
    out[(size_t)n * 256 + tid] = accv;
}

// ---------------- launch ----------------
extern "C" void kernel_launch(void* const* d_in, const int* in_sizes, int n_in,
                              void* d_out, int out_size) {
    const float* fm[5];
    for (int i = 0; i < 5; ++i) fm[i] = (const float*)d_in[i];
    const float* w_pre  = (const float*)d_in[5];
    const float* b_pre  = (const float*)d_in[6];
    const float* w_proj = (const float*)d_in[7];
    const float* b_proj = (const float*)d_in[8];
    const float* w_post = (const float*)d_in[9];
    const float* b_post = (const float*)d_in[10];
    float* out = (float*)d_out;

    const int convSmem = (2 * IB_FLOATS + 2 * WBQ_FLOATS) * 4;   // 44544 B
    cudaFuncSetAttribute(k_conv, cudaFuncAttributeMaxDynamicSharedMemorySize, convSmem);
    cudaFuncSetAttribute(k_top2, cudaFuncAttributeMaxDynamicSharedMemorySize, 16384 * 8);

    k_init<<<(2 * NLOGIT + 1023) / 1024, 1024>>>();
    k_wtrans<<<576, 1024>>>(w_pre);

    {
        dim3 grid(341, BB, 4);   // tiles x batch x oc-quarter
        k_conv<<<grid, 256, convSmem>>>(fm[0], fm[1], fm[2], fm[3], fm[4], b_pre, w_proj);
    }
    k_keys<<<(BB * NPOS + 255) / 256, 256>>>(b_proj);
    {
        dim3 grid(NCHUNK, BB);
        k_top1<<<grid, 512>>>();
    }
    k_top2<<<BB, 1024, 16384 * 8>>>();
    k_post<<<BB * KSEL, 256>>>(fm[0], fm[1], fm[2], fm[3], fm[4], w_post, b_post, out);
}

// round 9
// speedup vs baseline: 1.2033x; 1.2033x over previous
#include <cuda_runtime.h>
#include <cstdint>

typedef unsigned long long u64;
typedef unsigned int u32;

// ---------------- problem constants ----------------
#define BB 8
#define CC 256
#define NPOS 21824              // per-image positions across 5 maps
#define NANCH 196416            // NPOS * 9
#define NKEY 196608             // 48 * 4096 (padded)
#define KSEL 300
#define NCHUNK 48               // stage1 chunks of 4096 per image
#define NCAND (NCHUNK * KSEL)   // 14400 candidates per image
#define NLOGIT (BB * NPOS * 9)  // 1571328
#define NSEL (BB * KSEL)        // 2400

__device__ __constant__ int c_mapS[5]   = {128, 64, 32, 16, 8};
__device__ __constant__ int c_mapOff[5] = {0, 16384, 20480, 21504, 21760};

// ---------------- device scratch ----------------
__device__ float g_wT[256 * 9 * 256];            // [ic][tap][oc]
__device__ float g_logits[(size_t)NLOGIT];       // fused proj output (2-way atomic, commutative)
__device__ u64   g_keys[(size_t)BB * NKEY];
__device__ u64   g_cand[(size_t)BB * NCAND];
__device__ int   g_sel[NSEL];
__device__ int   g_cnt[9];
__device__ int   g_list[9 * NSEL];

// ---------------- f32x2 helpers ----------------
__device__ __forceinline__ u64 dup2(float x) {
    u64 r; asm("mov.b64 %0,{%1,%1};" : "=l"(r) : "f"(x)); return r;
}
__device__ __forceinline__ void ffma2(u64 &c, u64 a, u64 b) {
    asm("fma.rn.f32x2 %0,%1,%2,%3;" : "=l"(c) : "l"(a), "l"(b), "l"(c));
}
__device__ __forceinline__ void fadd2(u64 &c, u64 a) {
    asm("add.rn.f32x2 %0,%1,%2;" : "=l"(c) : "l"(c), "l"(a));
}
__device__ __forceinline__ float2 unpack2(u64 v) {
    float2 f; asm("mov.b64 {%0,%1},%2;" : "=f"(f.x), "=f"(f.y) : "l"(v)); return f;
}

// ---------------- kernel 0a: zero logits + key padding + group counters ----------------
__global__ void k_init() {
    int i = blockIdx.x * 1024 + threadIdx.x;
    if (i < NLOGIT) g_logits[i] = 0.f;
    if (i < BB * (NKEY - NANCH)) {
        int b = i / (NKEY - NANCH);
        int r = i - b * (NKEY - NANCH);
        g_keys[(size_t)b * NKEY + NANCH + r] = 0ull;
    }
    if (i < 9) g_cnt[i] = 0;
}

// ---------------- kernel 0b: weight transpose [oc][ic][t] -> [ic][t][oc] ----------------
__global__ void k_wtrans(const float* __restrict__ w_pre) {
    int i = blockIdx.x * 1024 + threadIdx.x;
    if (i >= 256 * 9 * 256) return;
    int oc = i & 255;
    int rest = i >> 8;
    int tap = rest % 9;
    int ic = rest / 9;
    g_wT[i] = w_pre[(oc * 256 + ic) * 9 + tap];
}

// ---------------- kernel 1: conv3x3 + bias + relu + fused 1x1 proj (R7 winner) --------
#define IB_FLOATS 960            // 8*10*12
#define WB_FLOATS 9216           // 8*9*128
#define W_CHUNK_BYTES 73728      // 8*9*256*4

#define LOADROW(dst, rr) { \
    float2 a_ = *(const float2*)(ib + (rr)*12); \
    float2 b_ = *(const float2*)(ib + (rr)*12 + 2); \
    dst[0] = dup2(a_.x); dst[1] = dup2(a_.y); \
    dst[2] = dup2(b_.x); dst[3] = dup2(b_.y); }

#define TAPROW(dy, top, bot) { \
    _Pragma("unroll") \
    for (int dx = 0; dx < 3; ++dx) { \
        const ulonglong2* wp = (const ulonglong2*)(wb + ((dy)*3 + dx) * 128); \
        ulonglong2 wA = wp[0]; \
        ulonglong2 wB = wp[1]; \
        ffma2(ch[0][0], top[dx],   wA.x); ffma2(ch[0][1], top[dx],   wA.y); \
        ffma2(ch[0][2], top[dx],   wB.x); ffma2(ch[0][3], top[dx],   wB.y); \
        ffma2(ch[1][0], top[dx+1], wA.x); ffma2(ch[1][1], top[dx+1], wA.y); \
        ffma2(ch[1][2], top[dx+1], wB.x); ffma2(ch[1][3], top[dx+1], wB.y); \
        ffma2(ch[2][0], bot[dx],   wA.x); ffma2(ch[2][1], bot[dx],   wA.y); \
        ffma2(ch[2][2], bot[dx],   wB.x); ffma2(ch[2][3], bot[dx],   wB.y); \
        ffma2(ch[3][0], bot[dx+1], wA.x); ffma2(ch[3][1], bot[dx+1], wA.y); \
        ffma2(ch[3][2], bot[dx+1], wB.x); ffma2(ch[3][3], bot[dx+1], wB.y); \
    } }

__global__ void __launch_bounds__(256, 2)
k_conv(const float* __restrict__ fm0, const float* __restrict__ fm1,
       const float* __restrict__ fm2, const float* __restrict__ fm3,
       const float* __restrict__ fm4, const float* __restrict__ b_pre,
       const float* __restrict__ w_proj) {
    extern __shared__ float sm[];
    float* ibuf[2] = {sm, sm + IB_FLOATS};
    float* wbuf[2] = {sm + 2 * IB_FLOATS, sm + 2 * IB_FLOATS + WB_FLOATS};
    const u32 smb = (u32)__cvta_generic_to_shared(sm);
    const u32 ibs[2] = {smb, smb + IB_FLOATS * 4};
    const u32 wbs[2] = {smb + 2 * IB_FLOATS * 4, smb + 2 * IB_FLOATS * 4 + WB_FLOATS * 4};

    const int tid = threadIdx.x;
    const int b = blockIdx.y;
    const int zh = blockIdx.z;

    int bx = blockIdx.x, m, tile;
    if (bx < 256)      { m = 0; tile = bx; }
    else if (bx < 320) { m = 1; tile = bx - 256; }
    else if (bx < 336) { m = 2; tile = bx - 320; }
    else if (bx < 340) { m = 3; tile = bx - 336; }
    else               { m = 4; tile = bx - 340; }
    const int s = c_mapS[m];
    const int HW = s * s;
    const int posOff = c_mapOff[m];
    const float* fm = (m == 0) ? fm0 : (m == 1) ? fm1 : (m == 2) ? fm2 : (m == 3) ? fm3 : fm4;

    const int tilesX = s >> 3;
    const int ty0 = (tile / tilesX) << 3;
    const int tx0 = (tile % tilesX) << 3;

    const int pg = tid & 15;
    const int og = tid >> 4;
    const int py = (pg >> 2) << 1;
    const int px = (pg & 3) << 1;

    const char* fb = (const char*)(fm + (size_t)b * 256 * HW);

    bool in_act[4];
    u32  in_so[4], in_go[4], in_sz[4];
#pragma unroll
    for (int k = 0; k < 4; ++k) {
        int idx = tid + (k << 8);
        in_act[k] = (idx < 800);
        int ii = in_act[k] ? idx : 0;
        int ic = ii / 100;
        int rem = ii - ic * 100;
        int r = rem / 10;
        int c = rem - 10 * r;
        int gy = ty0 - 1 + r, gx = tx0 - 1 + c;
        bool ok = (gy >= 0) && (gy < s) && (gx >= 0) && (gx < s);
        in_so[k] = (u32)(((ic * 10 + r) * 12 + c) * 4);
        in_go[k] = ok ? (u32)((ic * HW + gy * s + gx) * 4) : 0u;
        in_sz[k] = ok ? 4u : 0u;
    }
    u32 w_so[9], w_go[9];
#pragma unroll
    for (int k = 0; k < 9; ++k) {
        int i = tid + (k << 8);
        int icL = i / 288;
        int rem = i - icL * 288;
        int tap = rem >> 5;
        int q = rem & 31;
        w_so[k] = (u32)(i * 16);
        w_go[k] = (u32)(((((icL * 9 + tap) << 6) + (zh << 5) + q)) * 16);
    }
    const char* wtb = (const char*)g_wT;

    u64 acc[4][4];
#pragma unroll
    for (int p = 0; p < 4; ++p)
#pragma unroll
        for (int j = 0; j < 4; ++j) acc[p][j] = 0ull;

    {
#pragma unroll
        for (int k = 0; k < 4; ++k) if (in_act[k])
            asm volatile("cp.async.ca.shared.global [%0], [%1], 4, %2;"
                         :: "r"(ibs[0] + in_so[k]), "l"(fb + in_go[k]), "r"(in_sz[k]) : "memory");
#pragma unroll
        for (int k = 0; k < 9; ++k)
            asm volatile("cp.async.cg.shared.global [%0], [%1], 16;"
                         :: "r"(wbs[0] + w_so[k]), "l"(wtb + w_go[k]) : "memory");
        asm volatile("cp.async.commit_group;" ::: "memory");
    }

    const u32 inStride = (u32)(8 * HW * 4);

    for (int cc = 0; cc < 32; ++cc) {
        const int cur = cc & 1;
        asm volatile("cp.async.wait_group 0;" ::: "memory");
        __syncthreads();
        if (cc < 31) {
            const char* f = fb + (size_t)(cc + 1) * inStride;
            const char* w = wtb + (size_t)(cc + 1) * W_CHUNK_BYTES;
            const u32 ibS = ibs[cur ^ 1], wbS = wbs[cur ^ 1];
#pragma unroll
            for (int k = 0; k < 4; ++k) if (in_act[k])
                asm volatile("cp.async.ca.shared.global [%0], [%1], 4, %2;"
                             :: "r"(ibS + in_so[k]), "l"(f + in_go[k]), "r"(in_sz[k]) : "memory");
#pragma unroll
            for (int k = 0; k < 9; ++k)
                asm volatile("cp.async.cg.shared.global [%0], [%1], 16;"
                             :: "r"(wbS + w_so[k]), "l"(w + w_go[k]) : "memory");
            asm volatile("cp.async.commit_group;" ::: "memory");
        }

        u64 ch[4][4];
#pragma unroll
        for (int p = 0; p < 4; ++p)
#pragma unroll
            for (int j = 0; j < 4; ++j) ch[p][j] = 0ull;

        const float* ibase = ibuf[cur] + py * 12 + px;
        const float* wbase2 = wbuf[cur] + og * 8;
#pragma unroll
        for (int ic = 0; ic < 8; ++ic) {
            const float* ib = ibase + ic * 120;
            const float* wb = wbase2 + ic * 1152;
            u64 rA[4], rB[4];
            LOADROW(rA, 0);
            LOADROW(rB, 1);
            TAPROW(0, rA, rB);
            LOADROW(rA, 2);
            TAPROW(1, rB, rA);
            LOADROW(rB, 3);
            TAPROW(2, rA, rB);
        }
#pragma unroll
        for (int p = 0; p < 4; ++p)
#pragma unroll
            for (int j = 0; j < 4; ++j) fadd2(acc[p][j], ch[p][j]);
    }

    // ---- fused epilogue: bias + relu + 1x1 proj partials ----
    float part[4][9];
#pragma unroll
    for (int p = 0; p < 4; ++p)
#pragma unroll
        for (int a = 0; a < 9; ++a) part[p][a] = 0.f;

#pragma unroll
    for (int j = 0; j < 4; ++j) {
        const int oc = zh * 128 + og * 8 + 2 * j;
        const float b0 = b_pre[oc], b1 = b_pre[oc + 1];
#pragma unroll
        for (int p = 0; p < 4; ++p) {
            float2 v = unpack2(acc[p][j]);
            float r0 = fmaxf(v.x + b0, 0.f);
            float r1 = fmaxf(v.y + b1, 0.f);
#pragma unroll
            for (int a = 0; a < 9; ++a) {
                float t = part[p][a];
                t = fmaf(r0, w_proj[a * 256 + oc], t);
                t = fmaf(r1, w_proj[a * 256 + oc + 1], t);
                part[p][a] = t;
            }
        }
    }

    float* red = wbuf[0];
#pragma unroll
    for (int p = 0; p < 4; ++p) {
        int pl = (py + (p >> 1)) * 8 + (px + (p & 1));
#pragma unroll
        for (int a = 0; a < 9; ++a)
            red[(og * 64 + pl) * 9 + a] = part[p][a];
    }
    __syncthreads();

    for (int item = tid; item < 576; item += 256) {
        int pl = item / 9;
        int a = item - 9 * pl;
        float v = 0.f;
#pragma unroll
        for (int o = 0; o < 16; ++o)
            v += red[(o * 64 + pl) * 9 + a];
        int gy = ty0 + (pl >> 3);
        int gx = tx0 + (pl & 7);
        int pos = posOff + gy * s + gx;
        atomicAdd(&g_logits[((size_t)b * NPOS + pos) * 9 + a], v);
    }
}

// ---------------- kernel 2: logits -> sigmoid -> sortable keys ----------------
__global__ void __launch_bounds__(256)
k_keys(const float* __restrict__ b_proj) {
    int gid = blockIdx.x * 256 + threadIdx.x;
    if (gid >= BB * NPOS) return;
    int b = gid / NPOS;
    int p = gid - b * NPOS;
    const float* lg = g_logits + (size_t)gid * 9;
    u64* kb = g_keys + (size_t)b * NKEY + (size_t)p * 9;
#pragma unroll
    for (int a = 0; a < 9; ++a) {
        float logit = lg[a] + b_proj[a];
        float prob = 1.0f / (1.0f + expf(-logit));
        u32 pb = __float_as_uint(prob);
        u32 idx = (u32)(p * 9 + a);
        kb[a] = ((u64)pb << 32) | (u64)(0xFFFFFFFFu - idx);
    }
}

// ---------------- kernel 3: stage1 — tournament top-300 of each 4096 chunk ----------
// Phase A: sort eight 512-segments descending (45 half-passes).
// Phase B: 3 merge rounds; each keeps exact top-512 of a pair of sorted 512-lists
// (max(A[i], B[511-i]) forms a bitonic sequence; 9-pass descending clean sorts it).
// Final sk[0..511] = exact top-512 of 4096, sorted descending. Emit top 300.
__global__ void __launch_bounds__(512)
k_top1() {
    __shared__ u64 sk[4096];
    const int tid = threadIdx.x;
    const int blk = blockIdx.x;
    const int b = blockIdx.y;
    const u64* src = g_keys + (size_t)b * NKEY + (size_t)blk * 4096;
    for (int i = tid; i < 4096; i += 512) sk[i] = src[i];

    // Phase A
    for (int k = 2; k <= 512; k <<= 1) {
        for (int j = k >> 1; j > 0; j >>= 1) {
            __syncthreads();
            for (int t = tid; t < 2048; t += 512) {
                int i = ((t & ~(j - 1)) << 1) | (t & (j - 1));
                int il = i & 511;
                bool dir = ((il & k) == 0);
                u64 x = sk[i], y = sk[i + j];
                bool sw = dir ? (x < y) : (x > y);
                if (sw) { sk[i] = y; sk[i + j] = x; }
            }
        }
    }

    // Phase B: merge rounds (result segments: 4, 2, 1)
    for (int half = 4; half >= 1; half >>= 1) {
        const int nel = half * 512;
        __syncthreads();
        u64 va[4], vb[4];
        int cnt = 0;
        for (int e = tid; e < nel; e += 512, ++cnt) {
            int seg = e >> 9, i = e & 511;
            va[cnt] = sk[(seg * 2) * 512 + i];
            vb[cnt] = sk[(seg * 2 + 1) * 512 + 511 - i];
        }
        __syncthreads();
        cnt = 0;
        for (int e = tid; e < nel; e += 512, ++cnt)
            sk[e] = (va[cnt] > vb[cnt]) ? va[cnt] : vb[cnt];
        // clean each 512-seg (descending bitonic merge)
        for (int j = 256; j > 0; j >>= 1) {
            __syncthreads();
            for (int c = tid; c < half * 256; c += 512) {
                int seg = c >> 8, off = c & 255;
                int i = seg * 512 + (((off & ~(j - 1)) << 1) | (off & (j - 1)));
                u64 x = sk[i], y = sk[i + j];
                if (x < y) { sk[i] = y; sk[i + j] = x; }
            }
        }
    }
    __syncthreads();

    u64* dst = g_cand + ((size_t)b * NCHUNK + blk) * KSEL;
    for (int i = tid; i < KSEL; i += 512) dst[i] = sk[i];
}

// ---------------- kernel 4: stage2 — merge 14400 candidates per image ----------------
__device__ __forceinline__ void bitonic_step(u64* sk, int i, int j, int k) {
    int ixj = i | j;
    u64 a = sk[i], b = sk[ixj];
    bool dir = ((i & k) == 0);
    bool sw = dir ? (a < b) : (a > b);
    if (sw) { sk[i] = b; sk[ixj] = a; }
}

__global__ void __launch_bounds__(1024)
k_top2() {
    extern __shared__ u64 sk2[];   // 16384 keys = 128KB
    const int tid = threadIdx.x;
    const int b = blockIdx.x;
    const u64* src = g_cand + (size_t)b * NCAND;
    for (int i = tid; i < 16384; i += 1024) sk2[i] = (i < NCAND) ? src[i] : 0ull;
    for (int k = 2; k <= 16384; k <<= 1) {
        for (int j = k >> 1; j > 0; j >>= 1) {
            __syncthreads();
            for (int t = tid; t < 8192; t += 1024) {
                int i = ((t & ~(j - 1)) << 1) | (t & (j - 1));
                bitonic_step(sk2, i, j, k);
            }
        }
    }
    __syncthreads();
    if (tid < KSEL)
        g_sel[b * KSEL + tid] = (int)(0xFFFFFFFFu - (u32)(sk2[tid] & 0xFFFFFFFFull));
}

// ---------------- kernel 4b: group selected rows by cell-anchor ----------------
// Slot order within a list is schedule-dependent but does not affect any output
// value or location (each row's computation is slot-independent).
__global__ void __launch_bounds__(256)
k_group() {
    int n = blockIdx.x * 256 + threadIdx.x;
    if (n >= NSEL) return;
    int a = g_sel[n] % 9;
    int slot = atomicAdd(&g_cnt[a], 1);
    g_list[a * NSEL + slot] = n;
}

// ---------------- kernel 5: anchor-grouped gather + 256x256 matvec (8 rows/block) ----
__global__ void __launch_bounds__(256)
k_post(const float* __restrict__ fm0, const float* __restrict__ fm1,
       const float* __restrict__ fm2, const float* __restrict__ fm3,
       const float* __restrict__ fm4, const float* __restrict__ w_post,
       const float* __restrict__ b_post, float* __restrict__ out) {
    __shared__ float xs[8 * 256];
    const int a = blockIdx.y;
    const int start = blockIdx.x * 8;
    const int cnt = g_cnt[a];
    if (start >= cnt) return;
    const int tid = threadIdx.x;
    const int nr = min(8, cnt - start);

#pragma unroll
    for (int r = 0; r < 8; ++r) xs[r * 256 + tid] = 0.f;

    int rows[8];
    for (int r = 0; r < nr; ++r) {
        int n = g_list[a * NSEL + start + r];
        rows[r] = n;
        int b = n / KSEL;
        int pos = g_sel[n] / 9;
        int m, hw, HW;
        if (pos < 16384)      { m = 0; hw = pos;         HW = 16384; }
        else if (pos < 20480) { m = 1; hw = pos - 16384; HW = 4096;  }
        else if (pos < 21504) { m = 2; hw = pos - 20480; HW = 1024;  }
        else if (pos < 21760) { m = 3; hw = pos - 21504; HW = 256;   }
        else                  { m = 4; hw = pos - 21760; HW = 64;    }
        const float* fm = (m == 0) ? fm0 : (m == 1) ? fm1 : (m == 2) ? fm2 : (m == 3) ? fm3 : fm4;
        xs[r * 256 + tid] = fm[((size_t)b * 256 + tid) * HW + hw];
    }
    __syncthreads();

    const float* W = w_post + (size_t)a * 65536;
    const float bb = b_post[a * 256 + tid];
    float acc[8];
#pragma unroll
    for (int r = 0; r < 8; ++r) acc[r] = bb;

#pragma unroll 4
    for (int d = 0; d < 256; ++d) {
        float w = W[d * 256 + tid];
#pragma unroll
        for (int r = 0; r < 8; ++r)
            acc[r] = fmaf(xs[r * 256 + d], w, acc[r]);
    }
    for (int r = 0; r < nr; ++r)
        out[(size_t)rows[r] * 256 + tid] = acc[r];
}

// ---------------- launch ----------------
extern "C" void kernel_launch(void* const* d_in, const int* in_sizes, int n_in,
                              void* d_out, int out_size) {
    const float* fm[5];
    for (int i = 0; i < 5; ++i) fm[i] = (const float*)d_in[i];
    const float* w_pre  = (const float*)d_in[5];
    const float* b_pre  = (const float*)d_in[6];
    const float* w_proj = (const float*)d_in[7];
    const float* b_proj = (const float*)d_in[8];
    const float* w_post = (const float*)d_in[9];
    const float* b_post = (const float*)d_in[10];
    float* out = (float*)d_out;

    const int convSmem = (2 * IB_FLOATS + 2 * WB_FLOATS) * 4;   // 81408 B
    cudaFuncSetAttribute(k_conv, cudaFuncAttributeMaxDynamicSharedMemorySize, convSmem);
    cudaFuncSetAttribute(k_top2, cudaFuncAttributeMaxDynamicSharedMemorySize, 16384 * 8);

    k_init<<<(NLOGIT + 1023) / 1024, 1024>>>();
    k_wtrans<<<576, 1024>>>(w_pre);

    {
        dim3 grid(341, BB, 2);   // tiles x batch x oc-half
        k_conv<<<grid, 256, convSmem>>>(fm[0], fm[1], fm[2], fm[3], fm[4], b_pre, w_proj);
    }
    k_keys<<<(BB * NPOS + 255) / 256, 256>>>(b_proj);
    {
        dim3 grid(NCHUNK, BB);
        k_top1<<<grid, 512>>>();
    }
    k_top2<<<BB, 1024, 16384 * 8>>>();
    k_group<<<(NSEL + 255) / 256, 256>>>();
    {
        dim3 grid(NSEL / 8, 9);   // 300 x 9; blocks beyond per-anchor count exit early
        k_post<<<grid, 256>>>(fm[0], fm[1], fm[2], fm[3], fm[4], w_post, b_post, out);
    }
}

// round 12
// speedup vs baseline: 1.2062x; 1.0024x over previous
#include <cuda_runtime.h>
#include <cstdint>

typedef unsigned long long u64;
typedef unsigned int u32;

// ---------------- problem constants ----------------
#define BB 8
#define CC 256
#define NPOS 21824              // per-image positions across 5 maps
#define NANCH 196416            // NPOS * 9
#define NKEYPB 196608           // 48 * 4096 per image (virtual; keys built inline)
#define KSEL 300
#define NCHUNK 48               // stage1 chunks of 4096 per image
#define NCAND (NCHUNK * KSEL)   // 14400 candidates per image
#define NLOGIT (BB * NPOS * 9)  // 1571328
#define NSEL (BB * KSEL)        // 2400

__device__ __constant__ int c_mapS[5]   = {128, 64, 32, 16, 8};
__device__ __constant__ int c_mapOff[5] = {0, 16384, 20480, 21504, 21760};

// ---------------- device scratch ----------------
__device__ float g_wT[256 * 9 * 256];            // [ic][tap][oc]
__device__ float g_logits[(size_t)NLOGIT];       // fused proj output (2-way atomic, commutative)
__device__ u64   g_cand[(size_t)BB * NCAND];
__device__ int   g_sel[NSEL];
__device__ int   g_cnt[9];
__device__ int   g_list[9 * NSEL];

// ---------------- f32x2 helpers ----------------
__device__ __forceinline__ u64 dup2(float x) {
    u64 r; asm("mov.b64 %0,{%1,%1};" : "=l"(r) : "f"(x)); return r;
}
__device__ __forceinline__ void ffma2(u64 &c, u64 a, u64 b) {
    asm("fma.rn.f32x2 %0,%1,%2,%3;" : "=l"(c) : "l"(a), "l"(b), "l"(c));
}
__device__ __forceinline__ void fadd2(u64 &c, u64 a) {
    asm("add.rn.f32x2 %0,%1,%2;" : "=l"(c) : "l"(c), "l"(a));
}
__device__ __forceinline__ float2 unpack2(u64 v) {
    float2 f; asm("mov.b64 {%0,%1},%2;" : "=f"(f.x), "=f"(f.y) : "l"(v)); return f;
}

// ---------------- kernel 0: weight transpose + logit/counter zero (fused) ----------
__global__ void k_wtrans(const float* __restrict__ w_pre) {
    int i = blockIdx.x * 1024 + threadIdx.x;
    if (i < 256 * 9 * 256) {
        int oc = i & 255;
        int rest = i >> 8;
        int tap = rest % 9;
        int ic = rest / 9;
        g_wT[i] = w_pre[(oc * 256 + ic) * 9 + tap];
    }
    if (i < NLOGIT) g_logits[i] = 0.f;
    if (i < 9) g_cnt[i] = 0;
}

// ---------------- kernel 1: conv3x3 + bias + relu + fused 1x1 proj (R9 winner) -------
#define IB_FLOATS 960            // 8*10*12
#define WB_FLOATS 9216           // 8*9*128
#define W_CHUNK_BYTES 73728      // 8*9*256*4

#define LOADROW(dst, rr) { \
    float2 a_ = *(const float2*)(ib + (rr)*12); \
    float2 b_ = *(const float2*)(ib + (rr)*12 + 2); \
    dst[0] = dup2(a_.x); dst[1] = dup2(a_.y); \
    dst[2] = dup2(b_.x); dst[3] = dup2(b_.y); }

#define TAPROW(dy, top, bot) { \
    _Pragma("unroll") \
    for (int dx = 0; dx < 3; ++dx) { \
        const ulonglong2* wp = (const ulonglong2*)(wb + ((dy)*3 + dx) * 128); \
        ulonglong2 wA = wp[0]; \
        ulonglong2 wB = wp[1]; \
        ffma2(ch[0][0], top[dx],   wA.x); ffma2(ch[0][1], top[dx],   wA.y); \
        ffma2(ch[0][2], top[dx],   wB.x); ffma2(ch[0][3], top[dx],   wB.y); \
        ffma2(ch[1][0], top[dx+1], wA.x); ffma2(ch[1][1], top[dx+1], wA.y); \
        ffma2(ch[1][2], top[dx+1], wB.x); ffma2(ch[1][3], top[dx+1], wB.y); \
        ffma2(ch[2][0], bot[dx],   wA.x); ffma2(ch[2][1], bot[dx],   wA.y); \
        ffma2(ch[2][2], bot[dx],   wB.x); ffma2(ch[2][3], bot[dx],   wB.y); \
        ffma2(ch[3][0], bot[dx+1], wA.x); ffma2(ch[3][1], bot[dx+1], wA.y); \
        ffma2(ch[3][2], bot[dx+1], wB.x); ffma2(ch[3][3], bot[dx+1], wB.y); \
    } }

__global__ void __launch_bounds__(256, 2)
k_conv(const float* __restrict__ fm0, const float* __restrict__ fm1,
       const float* __restrict__ fm2, const float* __restrict__ fm3,
       const float* __restrict__ fm4, const float* __restrict__ b_pre,
       const float* __restrict__ w_proj) {
    extern __shared__ float sm[];
    float* ibuf[2] = {sm, sm + IB_FLOATS};
    float* wbuf[2] = {sm + 2 * IB_FLOATS, sm + 2 * IB_FLOATS + WB_FLOATS};
    const u32 smb = (u32)__cvta_generic_to_shared(sm);
    const u32 ibs[2] = {smb, smb + IB_FLOATS * 4};
    const u32 wbs[2] = {smb + 2 * IB_FLOATS * 4, smb + 2 * IB_FLOATS * 4 + WB_FLOATS * 4};

    const int tid = threadIdx.x;
    const int b = blockIdx.y;
    const int zh = blockIdx.z;

    int bx = blockIdx.x, m, tile;
    if (bx < 256)      { m = 0; tile = bx; }
    else if (bx < 320) { m = 1; tile = bx - 256; }
    else if (bx < 336) { m = 2; tile = bx - 320; }
    else if (bx < 340) { m = 3; tile = bx - 336; }
    else               { m = 4; tile = bx - 340; }
    const int s = c_mapS[m];
    const int HW = s * s;
    const int posOff = c_mapOff[m];
    const float* fm = (m == 0) ? fm0 : (m == 1) ? fm1 : (m == 2) ? fm2 : (m == 3) ? fm3 : fm4;

    const int tilesX = s >> 3;
    const int ty0 = (tile / tilesX) << 3;
    const int tx0 = (tile % tilesX) << 3;

    const int pg = tid & 15;
    const int og = tid >> 4;
    const int py = (pg >> 2) << 1;
    const int px = (pg & 3) << 1;

    const char* fb = (const char*)(fm + (size_t)b * 256 * HW);

    bool in_act[4];
    u32  in_so[4], in_go[4], in_sz[4];
#pragma unroll
    for (int k = 0; k < 4; ++k) {
        int idx = tid + (k << 8);
        in_act[k] = (idx < 800);
        int ii = in_act[k] ? idx : 0;
        int ic = ii / 100;
        int rem = ii - ic * 100;
        int r = rem / 10;
        int c = rem - 10 * r;
        int gy = ty0 - 1 + r, gx = tx0 - 1 + c;
        bool ok = (gy >= 0) && (gy < s) && (gx >= 0) && (gx < s);
        in_so[k] = (u32)(((ic * 10 + r) * 12 + c) * 4);
        in_go[k] = ok ? (u32)((ic * HW + gy * s + gx) * 4) : 0u;
        in_sz[k] = ok ? 4u : 0u;
    }
    u32 w_so[9], w_go[9];
#pragma unroll
    for (int k = 0; k < 9; ++k) {
        int i = tid + (k << 8);
        int icL = i / 288;
        int rem = i - icL * 288;
        int tap = rem >> 5;
        int q = rem & 31;
        w_so[k] = (u32)(i * 16);
        w_go[k] = (u32)(((((icL * 9 + tap) << 6) + (zh << 5) + q)) * 16);
    }
    const char* wtb = (const char*)g_wT;

    u64 acc[4][4];
#pragma unroll
    for (int p = 0; p < 4; ++p)
#pragma unroll
        for (int j = 0; j < 4; ++j) acc[p][j] = 0ull;

    {
#pragma unroll
        for (int k = 0; k < 4; ++k) if (in_act[k])
            asm volatile("cp.async.ca.shared.global [%0], [%1], 4, %2;"
                         :: "r"(ibs[0] + in_so[k]), "l"(fb + in_go[k]), "r"(in_sz[k]) : "memory");
#pragma unroll
        for (int k = 0; k < 9; ++k)
            asm volatile("cp.async.cg.shared.global [%0], [%1], 16;"
                         :: "r"(wbs[0] + w_so[k]), "l"(wtb + w_go[k]) : "memory");
        asm volatile("cp.async.commit_group;" ::: "memory");
    }

    const u32 inStride = (u32)(8 * HW * 4);

    for (int cc = 0; cc < 32; ++cc) {
        const int cur = cc & 1;
        asm volatile("cp.async.wait_group 0;" ::: "memory");
        __syncthreads();
        if (cc < 31) {
            const char* f = fb + (size_t)(cc + 1) * inStride;
            const char* w = wtb + (size_t)(cc + 1) * W_CHUNK_BYTES;
            const u32 ibS = ibs[cur ^ 1], wbS = wbs[cur ^ 1];
#pragma unroll
            for (int k = 0; k < 4; ++k) if (in_act[k])
                asm volatile("cp.async.ca.shared.global [%0], [%1], 4, %2;"
                             :: "r"(ibS + in_so[k]), "l"(f + in_go[k]), "r"(in_sz[k]) : "memory");
#pragma unroll
            for (int k = 0; k < 9; ++k)
                asm volatile("cp.async.cg.shared.global [%0], [%1], 16;"
                             :: "r"(wbS + w_so[k]), "l"(w + w_go[k]) : "memory");
            asm volatile("cp.async.commit_group;" ::: "memory");
        }

        u64 ch[4][4];
#pragma unroll
        for (int p = 0; p < 4; ++p)
#pragma unroll
            for (int j = 0; j < 4; ++j) ch[p][j] = 0ull;

        const float* ibase = ibuf[cur] + py * 12 + px;
        const float* wbase2 = wbuf[cur] + og * 8;
#pragma unroll
        for (int ic = 0; ic < 8; ++ic) {
            const float* ib = ibase + ic * 120;
            const float* wb = wbase2 + ic * 1152;
            u64 rA[4], rB[4];
            LOADROW(rA, 0);
            LOADROW(rB, 1);
            TAPROW(0, rA, rB);
            LOADROW(rA, 2);
            TAPROW(1, rB, rA);
            LOADROW(rB, 3);
            TAPROW(2, rA, rB);
        }
#pragma unroll
        for (int p = 0; p < 4; ++p)
#pragma unroll
            for (int j = 0; j < 4; ++j) fadd2(acc[p][j], ch[p][j]);
    }

    // ---- fused epilogue: bias + relu + 1x1 proj partials ----
    float part[4][9];
#pragma unroll
    for (int p = 0; p < 4; ++p)
#pragma unroll
        for (int a = 0; a < 9; ++a) part[p][a] = 0.f;

#pragma unroll
    for (int j = 0; j < 4; ++j) {
        const int oc = zh * 128 + og * 8 + 2 * j;
        const float b0 = b_pre[oc], b1 = b_pre[oc + 1];
#pragma unroll
        for (int p = 0; p < 4; ++p) {
            float2 v = unpack2(acc[p][j]);
            float r0 = fmaxf(v.x + b0, 0.f);
            float r1 = fmaxf(v.y + b1, 0.f);
#pragma unroll
            for (int a = 0; a < 9; ++a) {
                float t = part[p][a];
                t = fmaf(r0, w_proj[a * 256 + oc], t);
                t = fmaf(r1, w_proj[a * 256 + oc + 1], t);
                part[p][a] = t;
            }
        }
    }

    float* red = wbuf[0];
#pragma unroll
    for (int p = 0; p < 4; ++p) {
        int pl = (py + (p >> 1)) * 8 + (px + (p & 1));
#pragma unroll
        for (int a = 0; a < 9; ++a)
            red[(og * 64 + pl) * 9 + a] = part[p][a];
    }
    __syncthreads();

    for (int item = tid; item < 576; item += 256) {
        int pl = item / 9;
        int a = item - 9 * pl;
        float v = 0.f;
#pragma unroll
        for (int o = 0; o < 16; ++o)
            v += red[(o * 64 + pl) * 9 + a];
        int gy = ty0 + (pl >> 3);
        int gx = tx0 + (pl & 7);
        int pos = posOff + gy * s + gx;
        atomicAdd(&g_logits[((size_t)b * NPOS + pos) * 9 + a], v);
    }
}

// ---------------- kernel 3: stage1 — keys inline + tournament top-300 of 4096 -------
// Key construction fused from the former k_keys: bitwise-identical key values.
__global__ void __launch_bounds__(512)
k_top1(const float* __restrict__ b_proj) {
    __shared__ u64 sk[4096];
    const int tid = threadIdx.x;
    const int blk = blockIdx.x;
    const int b = blockIdx.y;
    const float* lg = g_logits + (size_t)b * NPOS * 9;

    for (int i = tid; i < 4096; i += 512) {
        int aidx = blk * 4096 + i;
        u64 key = 0ull;
        if (aidx < NANCH) {
            int p = aidx / 9;
            int a = aidx - 9 * p;
            float logit = lg[aidx] + b_proj[a];
            float prob = 1.0f / (1.0f + expf(-logit));
            u32 pb = __float_as_uint(prob);              // prob>0 => bit-monotonic
            key = ((u64)pb << 32) | (u64)(0xFFFFFFFFu - (u32)aidx);  // tie -> lower idx
        }
        sk[i] = key;
    }

    // Phase A: sort eight 512-segments descending
    for (int k = 2; k <= 512; k <<= 1) {
        for (int j = k >> 1; j > 0; j >>= 1) {
            __syncthreads();
            for (int t = tid; t < 2048; t += 512) {
                int i = ((t & ~(j - 1)) << 1) | (t & (j - 1));
                int il = i & 511;
                bool dir = ((il & k) == 0);
                u64 x = sk[i], y = sk[i + j];
                bool sw = dir ? (x < y) : (x > y);
                if (sw) { sk[i] = y; sk[i + j] = x; }
            }
        }
    }

    // Phase B: tournament merge rounds (exact top-512 of each pair)
    for (int half = 4; half >= 1; half >>= 1) {
        const int nel = half * 512;
        __syncthreads();
        u64 va[4], vb[4];
        int cnt = 0;
        for (int e = tid; e < nel; e += 512, ++cnt) {
            int seg = e >> 9, i = e & 511;
            va[cnt] = sk[(seg * 2) * 512 + i];
            vb[cnt] = sk[(seg * 2 + 1) * 512 + 511 - i];
        }
        __syncthreads();
        cnt = 0;
        for (int e = tid; e < nel; e += 512, ++cnt)
            sk[e] = (va[cnt] > vb[cnt]) ? va[cnt] : vb[cnt];
        for (int j = 256; j > 0; j >>= 1) {
            __syncthreads();
            for (int c = tid; c < half * 256; c += 512) {
                int seg = c >> 8, off = c & 255;
                int i = seg * 512 + (((off & ~(j - 1)) << 1) | (off & (j - 1)));
                u64 x = sk[i], y = sk[i + j];
                if (x < y) { sk[i] = y; sk[i + j] = x; }
            }
        }
    }
    __syncthreads();

    u64* dst = g_cand + ((size_t)b * NCHUNK + blk) * KSEL;
    for (int i = tid; i < KSEL; i += 512) dst[i] = sk[i];
}

// ---------------- kernel 4: stage2 — merge 14400 candidates per image ----------------
__device__ __forceinline__ void bitonic_step(u64* sk, int i, int j, int k) {
    int ixj = i | j;
    u64 a = sk[i], b = sk[ixj];
    bool dir = ((i & k) == 0);
    bool sw = dir ? (a < b) : (a > b);
    if (sw) { sk[i] = b; sk[ixj] = a; }
}

__global__ void __launch_bounds__(1024)
k_top2() {
    extern __shared__ u64 sk2[];   // 16384 keys = 128KB
    const int tid = threadIdx.x;
    const int b = blockIdx.x;
    const u64* src = g_cand + (size_t)b * NCAND;
    for (int i = tid; i < 16384; i += 1024) sk2[i] = (i < NCAND) ? src[i] : 0ull;
    for (int k = 2; k <= 16384; k <<= 1) {
        for (int j = k >> 1; j > 0; j >>= 1) {
            __syncthreads();
            for (int t = tid; t < 8192; t += 1024) {
                int i = ((t & ~(j - 1)) << 1) | (t & (j - 1));
                bitonic_step(sk2, i, j, k);
            }
        }
    }
    __syncthreads();
    if (tid < KSEL)
        g_sel[b * KSEL + tid] = (int)(0xFFFFFFFFu - (u32)(sk2[tid] & 0xFFFFFFFFull));
}

// ---------------- kernel 4b: group selected rows by cell-anchor ----------------
__global__ void __launch_bounds__(256)
k_group() {
    int n = blockIdx.x * 256 + threadIdx.x;
    if (n >= NSEL) return;
    int a = g_sel[n] % 9;
    int slot = atomicAdd(&g_cnt[a], 1);
    g_list[a * NSEL + slot] = n;
}

// ---------------- kernel 5: anchor-grouped gather + 256x256 matvec (8 rows/block) ----
__global__ void __launch_bounds__(256)
k_post(const float* __restrict__ fm0, const float* __restrict__ fm1,
       const float* __restrict__ fm2, const float* __restrict__ fm3,
       const float* __restrict__ fm4, const float* __restrict__ w_post,
       const float* __restrict__ b_post, float* __restrict__ out) {
    __shared__ float xs[8 * 256];
    const int a = blockIdx.y;
    const int start = blockIdx.x * 8;
    const int cnt = g_cnt[a];
    if (start >= cnt) return;
    const int tid = threadIdx.x;
    const int nr = min(8, cnt - start);

#pragma unroll
    for (int r = 0; r < 8; ++r) xs[r * 256 + tid] = 0.f;

    int rows[8];
    for (int r = 0; r < nr; ++r) {
        int n = g_list[a * NSEL + start + r];
        rows[r] = n;
        int b = n / KSEL;
        int pos = g_sel[n] / 9;
        int m, hw, HW;
        if (pos < 16384)      { m = 0; hw = pos;         HW = 16384; }
        else if (pos < 20480) { m = 1; hw = pos - 16384; HW = 4096;  }
        else if (pos < 21504) { m = 2; hw = pos - 20480; HW = 1024;  }
        else if (pos < 21760) { m = 3; hw = pos - 21504; HW = 256;   }
        else                  { m = 4; hw = pos - 21760; HW = 64;    }
        const float* fm = (m == 0) ? fm0 : (m == 1) ? fm1 : (m == 2) ? fm2 : (m == 3) ? fm3 : fm4;
        xs[r * 256 + tid] = fm[((size_t)b * 256 + tid) * HW + hw];
    }
    __syncthreads();

    const float* W = w_post + (size_t)a * 65536;
    const float bb = b_post[a * 256 + tid];
    float acc[8];
#pragma unroll
    for (int r = 0; r < 8; ++r) acc[r] = bb;

#pragma unroll 4
    for (int d = 0; d < 256; ++d) {
        float w = W[d * 256 + tid];
#pragma unroll
        for (int r = 0; r < 8; ++r)
            acc[r] = fmaf(xs[r * 256 + d], w, acc[r]);
    }
    for (int r = 0; r < nr; ++r)
        out[(size_t)rows[r] * 256 + tid] = acc[r];
}

// ---------------- launch ----------------
extern "C" void kernel_launch(void* const* d_in, const int* in_sizes, int n_in,
                              void* d_out, int out_size) {
    const float* fm[5];
    for (int i = 0; i < 5; ++i) fm[i] = (const float*)d_in[i];
    const float* w_pre  = (const float*)d_in[5];
    const float* b_pre  = (const float*)d_in[6];
    const float* w_proj = (const float*)d_in[7];
    const float* b_proj = (const float*)d_in[8];
    const float* w_post = (const float*)d_in[9];
    const float* b_post = (const float*)d_in[10];
    float* out = (float*)d_out;

    const int convSmem = (2 * IB_FLOATS + 2 * WB_FLOATS) * 4;   // 81408 B
    cudaFuncSetAttribute(k_conv, cudaFuncAttributeMaxDynamicSharedMemorySize, convSmem);
    cudaFuncSetAttribute(k_top2, cudaFuncAttributeMaxDynamicSharedMemorySize, 16384 * 8);

    // fused: weight transpose + logit zero + counter zero
    k_wtrans<<<(NLOGIT + 1023) / 1024, 1024>>>(w_pre);

    {
        dim3 grid(341, BB, 2);   // tiles x batch x oc-half
        k_conv<<<grid, 256, convSmem>>>(fm[0], fm[1], fm[2], fm[3], fm[4], b_pre, w_proj);
    }
    {
        dim3 grid(NCHUNK, BB);
        k_top1<<<grid, 512>>>(b_proj);
    }
    k_top2<<<BB, 1024, 16384 * 8>>>();
    k_group<<<(NSEL + 255) / 256, 256>>>();
    {
        dim3 grid(NSEL / 8, 9);
        k_post<<<grid, 256>>>(fm[0], fm[1], fm[2], fm[3], fm[4], w_post, b_post, out);
    }
}

// round 13
// speedup vs baseline: 1.2473x; 1.0341x over previous
#include <cuda_runtime.h>
#include <cstdint>

typedef unsigned long long u64;
typedef unsigned int u32;

// ---------------- problem constants ----------------
#define BB 8
#define CC 256
#define NPOS 21824              // per-image positions across 5 maps
#define NANCH 196416            // NPOS * 9
#define KSEL 300
#define NCHUNK 48               // stage1 chunks of 4096 per image
#define NCAND (NCHUNK * KSEL)   // 14400 candidates per image
#define NLOGIT (BB * NPOS * 9)  // 1571328
#define NSEL (BB * KSEL)        // 2400

__device__ __constant__ int c_mapS[5]   = {128, 64, 32, 16, 8};
__device__ __constant__ int c_mapOff[5] = {0, 16384, 20480, 21504, 21760};

// ---------------- device scratch ----------------
__device__ float g_wT[256 * 9 * 256];            // [ic][tap][oc]
__device__ float g_logits[(size_t)NLOGIT];       // fused proj output (2-way atomic, commutative)
__device__ u64   g_cand[(size_t)BB * NCAND];
__device__ int   g_sel[NSEL];
__device__ int   g_cnt[9];
__device__ int   g_list[9 * NSEL];

// ---------------- f32x2 helpers ----------------
__device__ __forceinline__ u64 dup2(float x) {
    u64 r; asm("mov.b64 %0,{%1,%1};" : "=l"(r) : "f"(x)); return r;
}
__device__ __forceinline__ void ffma2(u64 &c, u64 a, u64 b) {
    asm("fma.rn.f32x2 %0,%1,%2,%3;" : "=l"(c) : "l"(a), "l"(b), "l"(c));
}
__device__ __forceinline__ void fadd2(u64 &c, u64 a) {
    asm("add.rn.f32x2 %0,%1,%2;" : "=l"(c) : "l"(c), "l"(a));
}
__device__ __forceinline__ float2 unpack2(u64 v) {
    float2 f; asm("mov.b64 {%0,%1},%2;" : "=f"(f.x), "=f"(f.y) : "l"(v)); return f;
}

// ---------------- kernel 0: weight transpose + logit/counter zero (fused) ----------
__global__ void k_wtrans(const float* __restrict__ w_pre) {
    int i = blockIdx.x * 1024 + threadIdx.x;
    if (i < 256 * 9 * 256) {
        int oc = i & 255;
        int rest = i >> 8;
        int tap = rest % 9;
        int ic = rest / 9;
        g_wT[i] = w_pre[(oc * 256 + ic) * 9 + tap];
    }
    if (i < NLOGIT) g_logits[i] = 0.f;
    if (i < 9) g_cnt[i] = 0;
}

// ---------------- kernel 1: conv3x3 + bias + relu + fused 1x1 proj (R9 winner) -------
#define IB_FLOATS 960            // 8*10*12
#define WB_FLOATS 9216           // 8*9*128
#define W_CHUNK_BYTES 73728      // 8*9*256*4

#define LOADROW(dst, rr) { \
    float2 a_ = *(const float2*)(ib + (rr)*12); \
    float2 b_ = *(const float2*)(ib + (rr)*12 + 2); \
    dst[0] = dup2(a_.x); dst[1] = dup2(a_.y); \
    dst[2] = dup2(b_.x); dst[3] = dup2(b_.y); }

#define TAPROW(dy, top, bot) { \
    _Pragma("unroll") \
    for (int dx = 0; dx < 3; ++dx) { \
        const ulonglong2* wp = (const ulonglong2*)(wb + ((dy)*3 + dx) * 128); \
        ulonglong2 wA = wp[0]; \
        ulonglong2 wB = wp[1]; \
        ffma2(ch[0][0], top[dx],   wA.x); ffma2(ch[0][1], top[dx],   wA.y); \
        ffma2(ch[0][2], top[dx],   wB.x); ffma2(ch[0][3], top[dx],   wB.y); \
        ffma2(ch[1][0], top[dx+1], wA.x); ffma2(ch[1][1], top[dx+1], wA.y); \
        ffma2(ch[1][2], top[dx+1], wB.x); ffma2(ch[1][3], top[dx+1], wB.y); \
        ffma2(ch[2][0], bot[dx],   wA.x); ffma2(ch[2][1], bot[dx],   wA.y); \
        ffma2(ch[2][2], bot[dx],   wB.x); ffma2(ch[2][3], bot[dx],   wB.y); \
        ffma2(ch[3][0], bot[dx+1], wA.x); ffma2(ch[3][1], bot[dx+1], wA.y); \
        ffma2(ch[3][2], bot[dx+1], wB.x); ffma2(ch[3][3], bot[dx+1], wB.y); \
    } }

__global__ void __launch_bounds__(256, 2)
k_conv(const float* __restrict__ fm0, const float* __restrict__ fm1,
       const float* __restrict__ fm2, const float* __restrict__ fm3,
       const float* __restrict__ fm4, const float* __restrict__ b_pre,
       const float* __restrict__ w_proj) {
    extern __shared__ float sm[];
    float* ibuf[2] = {sm, sm + IB_FLOATS};
    float* wbuf[2] = {sm + 2 * IB_FLOATS, sm + 2 * IB_FLOATS + WB_FLOATS};
    const u32 smb = (u32)__cvta_generic_to_shared(sm);
    const u32 ibs[2] = {smb, smb + IB_FLOATS * 4};
    const u32 wbs[2] = {smb + 2 * IB_FLOATS * 4, smb + 2 * IB_FLOATS * 4 + WB_FLOATS * 4};

    const int tid = threadIdx.x;
    const int b = blockIdx.y;
    const int zh = blockIdx.z;

    int bx = blockIdx.x, m, tile;
    if (bx < 256)      { m = 0; tile = bx; }
    else if (bx < 320) { m = 1; tile = bx - 256; }
    else if (bx < 336) { m = 2; tile = bx - 320; }
    else if (bx < 340) { m = 3; tile = bx - 336; }
    else               { m = 4; tile = bx - 340; }
    const int s = c_mapS[m];
    const int HW = s * s;
    const int posOff = c_mapOff[m];
    const float* fm = (m == 0) ? fm0 : (m == 1) ? fm1 : (m == 2) ? fm2 : (m == 3) ? fm3 : fm4;

    const int tilesX = s >> 3;
    const int ty0 = (tile / tilesX) << 3;
    const int tx0 = (tile % tilesX) << 3;

    const int pg = tid & 15;
    const int og = tid >> 4;
    const int py = (pg >> 2) << 1;
    const int px = (pg & 3) << 1;

    const char* fb = (const char*)(fm + (size_t)b * 256 * HW);

    bool in_act[4];
    u32  in_so[4], in_go[4], in_sz[4];
#pragma unroll
    for (int k = 0; k < 4; ++k) {
        int idx = tid + (k << 8);
        in_act[k] = (idx < 800);
        int ii = in_act[k] ? idx : 0;
        int ic = ii / 100;
        int rem = ii - ic * 100;
        int r = rem / 10;
        int c = rem - 10 * r;
        int gy = ty0 - 1 + r, gx = tx0 - 1 + c;
        bool ok = (gy >= 0) && (gy < s) && (gx >= 0) && (gx < s);
        in_so[k] = (u32)(((ic * 10 + r) * 12 + c) * 4);
        in_go[k] = ok ? (u32)((ic * HW + gy * s + gx) * 4) : 0u;
        in_sz[k] = ok ? 4u : 0u;
    }
    u32 w_so[9], w_go[9];
#pragma unroll
    for (int k = 0; k < 9; ++k) {
        int i = tid + (k << 8);
        int icL = i / 288;
        int rem = i - icL * 288;
        int tap = rem >> 5;
        int q = rem & 31;
        w_so[k] = (u32)(i * 16);
        w_go[k] = (u32)(((((icL * 9 + tap) << 6) + (zh << 5) + q)) * 16);
    }
    const char* wtb = (const char*)g_wT;

    u64 acc[4][4];
#pragma unroll
    for (int p = 0; p < 4; ++p)
#pragma unroll
        for (int j = 0; j < 4; ++j) acc[p][j] = 0ull;

    {
#pragma unroll
        for (int k = 0; k < 4; ++k) if (in_act[k])
            asm volatile("cp.async.ca.shared.global [%0], [%1], 4, %2;"
                         :: "r"(ibs[0] + in_so[k]), "l"(fb + in_go[k]), "r"(in_sz[k]) : "memory");
#pragma unroll
        for (int k = 0; k < 9; ++k)
            asm volatile("cp.async.cg.shared.global [%0], [%1], 16;"
                         :: "r"(wbs[0] + w_so[k]), "l"(wtb + w_go[k]) : "memory");
        asm volatile("cp.async.commit_group;" ::: "memory");
    }

    const u32 inStride = (u32)(8 * HW * 4);

    for (int cc = 0; cc < 32; ++cc) {
        const int cur = cc & 1;
        asm volatile("cp.async.wait_group 0;" ::: "memory");
        __syncthreads();
        if (cc < 31) {
            const char* f = fb + (size_t)(cc + 1) * inStride;
            const char* w = wtb + (size_t)(cc + 1) * W_CHUNK_BYTES;
            const u32 ibS = ibs[cur ^ 1], wbS = wbs[cur ^ 1];
#pragma unroll
            for (int k = 0; k < 4; ++k) if (in_act[k])
                asm volatile("cp.async.ca.shared.global [%0], [%1], 4, %2;"
                             :: "r"(ibS + in_so[k]), "l"(f + in_go[k]), "r"(in_sz[k]) : "memory");
#pragma unroll
            for (int k = 0; k < 9; ++k)
                asm volatile("cp.async.cg.shared.global [%0], [%1], 16;"
                             :: "r"(wbS + w_so[k]), "l"(w + w_go[k]) : "memory");
            asm volatile("cp.async.commit_group;" ::: "memory");
        }

        u64 ch[4][4];
#pragma unroll
        for (int p = 0; p < 4; ++p)
#pragma unroll
            for (int j = 0; j < 4; ++j) ch[p][j] = 0ull;

        const float* ibase = ibuf[cur] + py * 12 + px;
        const float* wbase2 = wbuf[cur] + og * 8;
#pragma unroll
        for (int ic = 0; ic < 8; ++ic) {
            const float* ib = ibase + ic * 120;
            const float* wb = wbase2 + ic * 1152;
            u64 rA[4], rB[4];
            LOADROW(rA, 0);
            LOADROW(rB, 1);
            TAPROW(0, rA, rB);
            LOADROW(rA, 2);
            TAPROW(1, rB, rA);
            LOADROW(rB, 3);
            TAPROW(2, rA, rB);
        }
#pragma unroll
        for (int p = 0; p < 4; ++p)
#pragma unroll
            for (int j = 0; j < 4; ++j) fadd2(acc[p][j], ch[p][j]);
    }

    // ---- fused epilogue: bias + relu + 1x1 proj partials ----
    float part[4][9];
#pragma unroll
    for (int p = 0; p < 4; ++p)
#pragma unroll
        for (int a = 0; a < 9; ++a) part[p][a] = 0.f;

#pragma unroll
    for (int j = 0; j < 4; ++j) {
        const int oc = zh * 128 + og * 8 + 2 * j;
        const float b0 = b_pre[oc], b1 = b_pre[oc + 1];
#pragma unroll
        for (int p = 0; p < 4; ++p) {
            float2 v = unpack2(acc[p][j]);
            float r0 = fmaxf(v.x + b0, 0.f);
            float r1 = fmaxf(v.y + b1, 0.f);
#pragma unroll
            for (int a = 0; a < 9; ++a) {
                float t = part[p][a];
                t = fmaf(r0, w_proj[a * 256 + oc], t);
                t = fmaf(r1, w_proj[a * 256 + oc + 1], t);
                part[p][a] = t;
            }
        }
    }

    float* red = wbuf[0];
#pragma unroll
    for (int p = 0; p < 4; ++p) {
        int pl = (py + (p >> 1)) * 8 + (px + (p & 1));
#pragma unroll
        for (int a = 0; a < 9; ++a)
            red[(og * 64 + pl) * 9 + a] = part[p][a];
    }
    __syncthreads();

    for (int item = tid; item < 576; item += 256) {
        int pl = item / 9;
        int a = item - 9 * pl;
        float v = 0.f;
#pragma unroll
        for (int o = 0; o < 16; ++o)
            v += red[(o * 64 + pl) * 9 + a];
        int gy = ty0 + (pl >> 3);
        int gx = tx0 + (pl & 7);
        int pos = posOff + gy * s + gx;
        atomicAdd(&g_logits[((size_t)b * NPOS + pos) * 9 + a], v);
    }
}

// ---------------- kernel 3: stage1 — keys inline + tournament top-300 of 4096 -------
__global__ void __launch_bounds__(512)
k_top1(const float* __restrict__ b_proj) {
    __shared__ u64 sk[4096];
    const int tid = threadIdx.x;
    const int blk = blockIdx.x;
    const int b = blockIdx.y;
    const float* lg = g_logits + (size_t)b * NPOS * 9;

    for (int i = tid; i < 4096; i += 512) {
        int aidx = blk * 4096 + i;
        u64 key = 0ull;
        if (aidx < NANCH) {
            int p = aidx / 9;
            int a = aidx - 9 * p;
            float logit = lg[aidx] + b_proj[a];
            float prob = 1.0f / (1.0f + expf(-logit));
            u32 pb = __float_as_uint(prob);              // prob>0 => bit-monotonic
            key = ((u64)pb << 32) | (u64)(0xFFFFFFFFu - (u32)aidx);  // tie -> lower idx
        }
        sk[i] = key;
    }

    // Phase A: sort eight 512-segments descending
    for (int k = 2; k <= 512; k <<= 1) {
        for (int j = k >> 1; j > 0; j >>= 1) {
            __syncthreads();
            for (int t = tid; t < 2048; t += 512) {
                int i = ((t & ~(j - 1)) << 1) | (t & (j - 1));
                int il = i & 511;
                bool dir = ((il & k) == 0);
                u64 x = sk[i], y = sk[i + j];
                bool sw = dir ? (x < y) : (x > y);
                if (sw) { sk[i] = y; sk[i + j] = x; }
            }
        }
    }

    // Phase B: tournament merge rounds (exact top-512 of each pair)
    for (int half = 4; half >= 1; half >>= 1) {
        const int nel = half * 512;
        __syncthreads();
        u64 va[4], vb[4];
        int cnt = 0;
        for (int e = tid; e < nel; e += 512, ++cnt) {
            int seg = e >> 9, i = e & 511;
            va[cnt] = sk[(seg * 2) * 512 + i];
            vb[cnt] = sk[(seg * 2 + 1) * 512 + 511 - i];
        }
        __syncthreads();
        cnt = 0;
        for (int e = tid; e < nel; e += 512, ++cnt)
            sk[e] = (va[cnt] > vb[cnt]) ? va[cnt] : vb[cnt];
        for (int j = 256; j > 0; j >>= 1) {
            __syncthreads();
            for (int c = tid; c < half * 256; c += 512) {
                int seg = c >> 8, off = c & 255;
                int i = seg * 512 + (((off & ~(j - 1)) << 1) | (off & (j - 1)));
                u64 x = sk[i], y = sk[i + j];
                if (x < y) { sk[i] = y; sk[i + j] = x; }
            }
        }
    }
    __syncthreads();

    u64* dst = g_cand + ((size_t)b * NCHUNK + blk) * KSEL;
    for (int i = tid; i < KSEL; i += 512) dst[i] = sk[i];
}

// ---------------- kernel 4: stage2 — tournament merge of 48 sorted 300-lists -------
// Input lists are sorted descending (k_top1 emits sorted prefixes). Zero-pad each
// to 512 -> still sorted. Pair-merge C[i]=max(A[i],B[511-i]) keeps the EXACT
// top-512 of the pair (bitonic half-cleaner); 9-pass clean re-sorts each segment.
// Rounds: 48->24 (from global) ->12->6->3, then two 2-way merges -> exact sorted
// top-512 of all 14400; emit top 300. Selection identical to a full sort.
__device__ __forceinline__ void t2_clean(u64* sk, int nseg, int tid) {
    for (int j = 256; j > 0; j >>= 1) {
        __syncthreads();
        for (int c = tid; c < nseg * 256; c += 1024) {
            int seg = c >> 8, off = c & 255;
            int i = seg * 512 + (((off & ~(j - 1)) << 1) | (off & (j - 1)));
            u64 x = sk[i], y = sk[i + j];
            if (x < y) { sk[i] = y; sk[i + j] = x; }
        }
    }
}

__global__ void __launch_bounds__(1024)
k_top2() {
    extern __shared__ u64 sk2[];   // 24 * 512 keys = 96 KB
    const int tid = threadIdx.x;
    const int b = blockIdx.x;
    const u64* src = g_cand + (size_t)b * NCAND;

    // Round 1: 48 global lists -> 24 smem segments (no staging needed: src is global)
    for (int e = tid; e < 24 * 512; e += 1024) {
        int seg = e >> 9, i = e & 511;
        u64 a = (i < KSEL) ? src[(seg * 2) * KSEL + i] : 0ull;
        int ri = 511 - i;
        u64 c = (ri < KSEL) ? src[(seg * 2 + 1) * KSEL + ri] : 0ull;
        sk2[e] = (a > c) ? a : c;
    }
    t2_clean(sk2, 24, tid);

    // Rounds 24->12, 12->6, 6->3
    for (int nsegO = 12; nsegO >= 3; nsegO >>= 1) {
        const int nel = nsegO * 512;
        __syncthreads();
        u64 va[6], vb[6];
        int cnt = 0;
        for (int e = tid; e < nel; e += 1024, ++cnt) {
            int seg = e >> 9, i = e & 511;
            va[cnt] = sk2[(seg * 2) * 512 + i];
            vb[cnt] = sk2[(seg * 2 + 1) * 512 + 511 - i];
        }
        __syncthreads();
        cnt = 0;
        for (int e = tid; e < nel; e += 1024, ++cnt)
            sk2[e] = (va[cnt] > vb[cnt]) ? va[cnt] : vb[cnt];
        t2_clean(sk2, nsegO, tid);
    }

    // 3 segments left: merge(0,1) -> 0, then merge(0,2) -> 0
    for (int other = 1; other <= 2; ++other) {
        __syncthreads();
        u64 va0 = 0, vb0 = 0;
        if (tid < 512) {
            va0 = sk2[tid];
            vb0 = sk2[other * 512 + 511 - tid];
        }
        __syncthreads();
        if (tid < 512) sk2[tid] = (va0 > vb0) ? va0 : vb0;
        t2_clean(sk2, 1, tid);
    }
    __syncthreads();

    if (tid < KSEL)
        g_sel[b * KSEL + tid] = (int)(0xFFFFFFFFu - (u32)(sk2[tid] & 0xFFFFFFFFull));
}

// ---------------- kernel 4b: group selected rows by cell-anchor ----------------
__global__ void __launch_bounds__(256)
k_group() {
    int n = blockIdx.x * 256 + threadIdx.x;
    if (n >= NSEL) return;
    int a = g_sel[n] % 9;
    int slot = atomicAdd(&g_cnt[a], 1);
    g_list[a * NSEL + slot] = n;
}

// ---------------- kernel 5: anchor-grouped gather + 256x256 matvec (8 rows/block) ----
__global__ void __launch_bounds__(256)
k_post(const float* __restrict__ fm0, const float* __restrict__ fm1,
       const float* __restrict__ fm2, const float* __restrict__ fm3,
       const float* __restrict__ fm4, const float* __restrict__ w_post,
       const float* __restrict__ b_post, float* __restrict__ out) {
    __shared__ float xs[8 * 256];
    const int a = blockIdx.y;
    const int start = blockIdx.x * 8;
    const int cnt = g_cnt[a];
    if (start >= cnt) return;
    const int tid = threadIdx.x;
    const int nr = min(8, cnt - start);

#pragma unroll
    for (int r = 0; r < 8; ++r) xs[r * 256 + tid] = 0.f;

    int rows[8];
    for (int r = 0; r < nr; ++r) {
        int n = g_list[a * NSEL + start + r];
        rows[r] = n;
        int b = n / KSEL;
        int pos = g_sel[n] / 9;
        int m, hw, HW;
        if (pos < 16384)      { m = 0; hw = pos;         HW = 16384; }
        else if (pos < 20480) { m = 1; hw = pos - 16384; HW = 4096;  }
        else if (pos < 21504) { m = 2; hw = pos - 20480; HW = 1024;  }
        else if (pos < 21760) { m = 3; hw = pos - 21504; HW = 256;   }
        else                  { m = 4; hw = pos - 21760; HW = 64;    }
        const float* fm = (m == 0) ? fm0 : (m == 1) ? fm1 : (m == 2) ? fm2 : (m == 3) ? fm3 : fm4;
        xs[r * 256 + tid] = fm[((size_t)b * 256 + tid) * HW + hw];
    }
    __syncthreads();

    const float* W = w_post + (size_t)a * 65536;
    const float bb = b_post[a * 256 + tid];
    float acc[8];
#pragma unroll
    for (int r = 0; r < 8; ++r) acc[r] = bb;

#pragma unroll 4
    for (int d = 0; d < 256; ++d) {
        float w = W[d * 256 + tid];
#pragma unroll
        for (int r = 0; r < 8; ++r)
            acc[r] = fmaf(xs[r * 256 + d], w, acc[r]);
    }
    for (int r = 0; r < nr; ++r)
        out[(size_t)rows[r] * 256 + tid] = acc[r];
}

// ---------------- launch ----------------
extern "C" void kernel_launch(void* const* d_in, const int* in_sizes, int n_in,
                              void* d_out, int out_size) {
    const float* fm[5];
    for (int i = 0; i < 5; ++i) fm[i] = (const float*)d_in[i];
    const float* w_pre  = (const float*)d_in[5];
    const float* b_pre  = (const float*)d_in[6];
    const float* w_proj = (const float*)d_in[7];
    const float* b_proj = (const float*)d_in[8];
    const float* w_post = (const float*)d_in[9];
    const float* b_post = (const float*)d_in[10];
    float* out = (float*)d_out;

    const int convSmem = (2 * IB_FLOATS + 2 * WB_FLOATS) * 4;   // 81408 B
    const int top2Smem = 24 * 512 * 8;                          // 98304 B
    cudaFuncSetAttribute(k_conv, cudaFuncAttributeMaxDynamicSharedMemorySize, convSmem);
    cudaFuncSetAttribute(k_top2, cudaFuncAttributeMaxDynamicSharedMemorySize, top2Smem);

    // fused: weight transpose + logit zero + counter zero
    k_wtrans<<<(NLOGIT + 1023) / 1024, 1024>>>(w_pre);

    {
        dim3 grid(341, BB, 2);   // tiles x batch x oc-half
        k_conv<<<grid, 256, convSmem>>>(fm[0], fm[1], fm[2], fm[3], fm[4], b_pre, w_proj);
    }
    {
        dim3 grid(NCHUNK, BB);
        k_top1<<<grid, 512>>>(b_proj);
    }
    k_top2<<<BB, 1024, top2Smem>>>();
    k_group<<<(NSEL + 255) / 256, 256>>>();
    {
        dim3 grid(NSEL / 8, 9);
        k_post<<<grid, 256>>>(fm[0], fm[1], fm[2], fm[3], fm[4], w_post, b_post, out);
    }
}

// round 14
// speedup vs baseline: 1.2523x; 1.0040x over previous
#include <cuda_runtime.h>
#include <cstdint>

typedef unsigned long long u64;
typedef unsigned int u32;

// ---------------- problem constants ----------------
#define BB 8
#define CC 256
#define NPOS 21824              // per-image positions across 5 maps
#define NANCH 196416            // NPOS * 9
#define KSEL 300
#define NCHUNK 48               // stage1 chunks of 4096 per image
#define NCAND (NCHUNK * KSEL)   // 14400 candidates per image
#define NLOGIT (BB * NPOS * 9)  // 1571328
#define NSEL (BB * KSEL)        // 2400

__device__ __constant__ int c_mapS[5]   = {128, 64, 32, 16, 8};
__device__ __constant__ int c_mapOff[5] = {0, 16384, 20480, 21504, 21760};

// ---------------- device scratch ----------------
__device__ float g_wT[256 * 9 * 256];            // [ic][tap][oc]
__device__ float g_logits[(size_t)NLOGIT];       // fused proj output (2-way atomic, commutative)
__device__ u64   g_cand[(size_t)BB * NCAND];
__device__ int   g_sel[NSEL];
__device__ int   g_cnt[9];
__device__ int   g_list[9 * NSEL];

// ---------------- f32x2 helpers ----------------
__device__ __forceinline__ u64 dup2(float x) {
    u64 r; asm("mov.b64 %0,{%1,%1};" : "=l"(r) : "f"(x)); return r;
}
__device__ __forceinline__ void ffma2(u64 &c, u64 a, u64 b) {
    asm("fma.rn.f32x2 %0,%1,%2,%3;" : "=l"(c) : "l"(a), "l"(b), "l"(c));
}
__device__ __forceinline__ void fadd2(u64 &c, u64 a) {
    asm("add.rn.f32x2 %0,%1,%2;" : "=l"(c) : "l"(c), "l"(a));
}
__device__ __forceinline__ float2 unpack2(u64 v) {
    float2 f; asm("mov.b64 {%0,%1},%2;" : "=f"(f.x), "=f"(f.y) : "l"(v)); return f;
}

// ---------------- kernel 0: weight transpose + logit/counter zero (fused) ----------
__global__ void k_wtrans(const float* __restrict__ w_pre) {
    int i = blockIdx.x * 1024 + threadIdx.x;
    if (i < 256 * 9 * 256) {
        int oc = i & 255;
        int rest = i >> 8;
        int tap = rest % 9;
        int ic = rest / 9;
        g_wT[i] = w_pre[(oc * 256 + ic) * 9 + tap];
    }
    if (i < NLOGIT) g_logits[i] = 0.f;
    if (i < 9) g_cnt[i] = 0;
}

// ---------------- kernel 1: conv3x3 + bias + relu + fused 1x1 proj (R9 winner) -------
#define IB_FLOATS 960            // 8*10*12
#define WB_FLOATS 9216           // 8*9*128
#define W_CHUNK_BYTES 73728      // 8*9*256*4

#define LOADROW(dst, rr) { \
    float2 a_ = *(const float2*)(ib + (rr)*12); \
    float2 b_ = *(const float2*)(ib + (rr)*12 + 2); \
    dst[0] = dup2(a_.x); dst[1] = dup2(a_.y); \
    dst[2] = dup2(b_.x); dst[3] = dup2(b_.y); }

#define TAPROW(dy, top, bot) { \
    _Pragma("unroll") \
    for (int dx = 0; dx < 3; ++dx) { \
        const ulonglong2* wp = (const ulonglong2*)(wb + ((dy)*3 + dx) * 128); \
        ulonglong2 wA = wp[0]; \
        ulonglong2 wB = wp[1]; \
        ffma2(ch[0][0], top[dx],   wA.x); ffma2(ch[0][1], top[dx],   wA.y); \
        ffma2(ch[0][2], top[dx],   wB.x); ffma2(ch[0][3], top[dx],   wB.y); \
        ffma2(ch[1][0], top[dx+1], wA.x); ffma2(ch[1][1], top[dx+1], wA.y); \
        ffma2(ch[1][2], top[dx+1], wB.x); ffma2(ch[1][3], top[dx+1], wB.y); \
        ffma2(ch[2][0], bot[dx],   wA.x); ffma2(ch[2][1], bot[dx],   wA.y); \
        ffma2(ch[2][2], bot[dx],   wB.x); ffma2(ch[2][3], bot[dx],   wB.y); \
        ffma2(ch[3][0], bot[dx+1], wA.x); ffma2(ch[3][1], bot[dx+1], wA.y); \
        ffma2(ch[3][2], bot[dx+1], wB.x); ffma2(ch[3][3], bot[dx+1], wB.y); \
    } }

__global__ void __launch_bounds__(256, 2)
k_conv(const float* __restrict__ fm0, const float* __restrict__ fm1,
       const float* __restrict__ fm2, const float* __restrict__ fm3,
       const float* __restrict__ fm4, const float* __restrict__ b_pre,
       const float* __restrict__ w_proj) {
    extern __shared__ float sm[];
    float* ibuf[2] = {sm, sm + IB_FLOATS};
    float* wbuf[2] = {sm + 2 * IB_FLOATS, sm + 2 * IB_FLOATS + WB_FLOATS};
    const u32 smb = (u32)__cvta_generic_to_shared(sm);
    const u32 ibs[2] = {smb, smb + IB_FLOATS * 4};
    const u32 wbs[2] = {smb + 2 * IB_FLOATS * 4, smb + 2 * IB_FLOATS * 4 + WB_FLOATS * 4};

    const int tid = threadIdx.x;
    const int b = blockIdx.y;
    const int zh = blockIdx.z;

    int bx = blockIdx.x, m, tile;
    if (bx < 256)      { m = 0; tile = bx; }
    else if (bx < 320) { m = 1; tile = bx - 256; }
    else if (bx < 336) { m = 2; tile = bx - 320; }
    else if (bx < 340) { m = 3; tile = bx - 336; }
    else               { m = 4; tile = bx - 340; }
    const int s = c_mapS[m];
    const int HW = s * s;
    const int posOff = c_mapOff[m];
    const float* fm = (m == 0) ? fm0 : (m == 1) ? fm1 : (m == 2) ? fm2 : (m == 3) ? fm3 : fm4;

    const int tilesX = s >> 3;
    const int ty0 = (tile / tilesX) << 3;
    const int tx0 = (tile % tilesX) << 3;

    const int pg = tid & 15;
    const int og = tid >> 4;
    const int py = (pg >> 2) << 1;
    const int px = (pg & 3) << 1;

    const char* fb = (const char*)(fm + (size_t)b * 256 * HW);

    bool in_act[4];
    u32  in_so[4], in_go[4], in_sz[4];
#pragma unroll
    for (int k = 0; k < 4; ++k) {
        int idx = tid + (k << 8);
        in_act[k] = (idx < 800);
        int ii = in_act[k] ? idx : 0;
        int ic = ii / 100;
        int rem = ii - ic * 100;
        int r = rem / 10;
        int c = rem - 10 * r;
        int gy = ty0 - 1 + r, gx = tx0 - 1 + c;
        bool ok = (gy >= 0) && (gy < s) && (gx >= 0) && (gx < s);
        in_so[k] = (u32)(((ic * 10 + r) * 12 + c) * 4);
        in_go[k] = ok ? (u32)((ic * HW + gy * s + gx) * 4) : 0u;
        in_sz[k] = ok ? 4u : 0u;
    }
    u32 w_so[9], w_go[9];
#pragma unroll
    for (int k = 0; k < 9; ++k) {
        int i = tid + (k << 8);
        int icL = i / 288;
        int rem = i - icL * 288;
        int tap = rem >> 5;
        int q = rem & 31;
        w_so[k] = (u32)(i * 16);
        w_go[k] = (u32)(((((icL * 9 + tap) << 6) + (zh << 5) + q)) * 16);
    }
    const char* wtb = (const char*)g_wT;

    u64 acc[4][4];
#pragma unroll
    for (int p = 0; p < 4; ++p)
#pragma unroll
        for (int j = 0; j < 4; ++j) acc[p][j] = 0ull;

    {
#pragma unroll
        for (int k = 0; k < 4; ++k) if (in_act[k])
            asm volatile("cp.async.ca.shared.global [%0], [%1], 4, %2;"
                         :: "r"(ibs[0] + in_so[k]), "l"(fb + in_go[k]), "r"(in_sz[k]) : "memory");
#pragma unroll
        for (int k = 0; k < 9; ++k)
            asm volatile("cp.async.cg.shared.global [%0], [%1], 16;"
                         :: "r"(wbs[0] + w_so[k]), "l"(wtb + w_go[k]) : "memory");
        asm volatile("cp.async.commit_group;" ::: "memory");
    }

    const u32 inStride = (u32)(8 * HW * 4);

    for (int cc = 0; cc < 32; ++cc) {
        const int cur = cc & 1;
        asm volatile("cp.async.wait_group 0;" ::: "memory");
        __syncthreads();
        if (cc < 31) {
            const char* f = fb + (size_t)(cc + 1) * inStride;
            const char* w = wtb + (size_t)(cc + 1) * W_CHUNK_BYTES;
            const u32 ibS = ibs[cur ^ 1], wbS = wbs[cur ^ 1];
#pragma unroll
            for (int k = 0; k < 4; ++k) if (in_act[k])
                asm volatile("cp.async.ca.shared.global [%0], [%1], 4, %2;"
                             :: "r"(ibS + in_so[k]), "l"(f + in_go[k]), "r"(in_sz[k]) : "memory");
#pragma unroll
            for (int k = 0; k < 9; ++k)
                asm volatile("cp.async.cg.shared.global [%0], [%1], 16;"
                             :: "r"(wbS + w_so[k]), "l"(w + w_go[k]) : "memory");
            asm volatile("cp.async.commit_group;" ::: "memory");
        }

        u64 ch[4][4];
#pragma unroll
        for (int p = 0; p < 4; ++p)
#pragma unroll
            for (int j = 0; j < 4; ++j) ch[p][j] = 0ull;

        const float* ibase = ibuf[cur] + py * 12 + px;
        const float* wbase2 = wbuf[cur] + og * 8;
#pragma unroll
        for (int ic = 0; ic < 8; ++ic) {
            const float* ib = ibase + ic * 120;
            const float* wb = wbase2 + ic * 1152;
            u64 rA[4], rB[4];
            LOADROW(rA, 0);
            LOADROW(rB, 1);
            TAPROW(0, rA, rB);
            LOADROW(rA, 2);
            TAPROW(1, rB, rA);
            LOADROW(rB, 3);
            TAPROW(2, rA, rB);
        }
#pragma unroll
        for (int p = 0; p < 4; ++p)
#pragma unroll
            for (int j = 0; j < 4; ++j) fadd2(acc[p][j], ch[p][j]);
    }

    // ---- fused epilogue: bias + relu + 1x1 proj partials ----
    float part[4][9];
#pragma unroll
    for (int p = 0; p < 4; ++p)
#pragma unroll
        for (int a = 0; a < 9; ++a) part[p][a] = 0.f;

#pragma unroll
    for (int j = 0; j < 4; ++j) {
        const int oc = zh * 128 + og * 8 + 2 * j;
        const float b0 = b_pre[oc], b1 = b_pre[oc + 1];
#pragma unroll
        for (int p = 0; p < 4; ++p) {
            float2 v = unpack2(acc[p][j]);
            float r0 = fmaxf(v.x + b0, 0.f);
            float r1 = fmaxf(v.y + b1, 0.f);
#pragma unroll
            for (int a = 0; a < 9; ++a) {
                float t = part[p][a];
                t = fmaf(r0, w_proj[a * 256 + oc], t);
                t = fmaf(r1, w_proj[a * 256 + oc + 1], t);
                part[p][a] = t;
            }
        }
    }

    float* red = wbuf[0];
#pragma unroll
    for (int p = 0; p < 4; ++p) {
        int pl = (py + (p >> 1)) * 8 + (px + (p & 1));
#pragma unroll
        for (int a = 0; a < 9; ++a)
            red[(og * 64 + pl) * 9 + a] = part[p][a];
    }
    __syncthreads();

    for (int item = tid; item < 576; item += 256) {
        int pl = item / 9;
        int a = item - 9 * pl;
        float v = 0.f;
#pragma unroll
        for (int o = 0; o < 16; ++o)
            v += red[(o * 64 + pl) * 9 + a];
        int gy = ty0 + (pl >> 3);
        int gx = tx0 + (pl & 7);
        int pos = posOff + gy * s + gx;
        atomicAdd(&g_logits[((size_t)b * NPOS + pos) * 9 + a], v);
    }
}

// ---------------- warp-level bitonic sort (descending) of 256 keys, 8/lane ----------
// XOR network: partner of element e at step j is e^j; direction from (e & k).
// Elements: e = r*32 + lane. j>=32 -> intra-thread reg pair (r, r|jr); j<32 -> shfl_xor.
__device__ __forceinline__ void warp_sort256_desc(u64 v[8], int lane) {
#pragma unroll
    for (int k = 2; k <= 256; k <<= 1) {
#pragma unroll
        for (int j = k >> 1; j > 0; j >>= 1) {
            if (j >= 32) {
                const int jr = j >> 5;
#pragma unroll
                for (int r = 0; r < 8; ++r) {
                    if ((r & jr) == 0) {
                        const int r2 = r | jr;
                        const bool wantmax = (((r * 32) & k) == 0);  // e&k (k>=64 here)
                        u64 a = v[r], bq = v[r2];
                        u64 mx = a > bq ? a : bq;
                        u64 mn = a > bq ? bq : a;
                        v[r]  = wantmax ? mx : mn;
                        v[r2] = wantmax ? mn : mx;
                    }
                }
            } else {
#pragma unroll
                for (int r = 0; r < 8; ++r) {
                    u64 p = __shfl_xor_sync(0xFFFFFFFFu, v[r], j);
                    const int eak = (k >= 32) ? ((r * 32) & k) : (lane & k);
                    const bool wantmax = (eak == 0);
                    const bool is_low = ((lane & j) == 0);
                    const bool takemax = (is_low == wantmax);
                    u64 mx = v[r] > p ? v[r] : p;
                    u64 mn = v[r] > p ? p : v[r];
                    v[r] = takemax ? mx : mn;
                }
            }
        }
    }
}

// ---------------- kernel 3: stage1 — keys inline + warp sort + tournament top-300 ----
__global__ void __launch_bounds__(512)
k_top1(const float* __restrict__ b_proj) {
    __shared__ u64 sk[4096];
    const int tid = threadIdx.x;
    const int lane = tid & 31;
    const int w = tid >> 5;               // warp 0..15, segment of 256 keys
    const int blk = blockIdx.x;
    const int b = blockIdx.y;
    const float* lg = g_logits + (size_t)b * NPOS * 9;

    // Phase A: build keys in registers, warp-sort 256 descending, write to smem
    u64 v[8];
#pragma unroll
    for (int r = 0; r < 8; ++r) {
        int aidx = blk * 4096 + w * 256 + r * 32 + lane;
        u64 key = 0ull;
        if (aidx < NANCH) {
            int p = aidx / 9;
            int a = aidx - 9 * p;
            float logit = lg[aidx] + b_proj[a];
            float prob = 1.0f / (1.0f + expf(-logit));
            u32 pb = __float_as_uint(prob);              // prob>0 => bit-monotonic
            key = ((u64)pb << 32) | (u64)(0xFFFFFFFFu - (u32)aidx);  // tie -> lower idx
        }
        v[r] = key;
    }
    warp_sort256_desc(v, lane);
#pragma unroll
    for (int r = 0; r < 8; ++r)
        sk[w * 256 + r * 32 + lane] = v[r];
    __syncthreads();

    // Full merge 16x256 -> 8x512 (no truncation): build bitonic (desc | reversed-desc)
    {
        u64 tv[8];
        int c = 0;
        for (int x = tid; x < 4096; x += 512, ++c) {
            int sseg = x >> 9, i = x & 511;
            tv[c] = (i < 256) ? sk[(2 * sseg) * 256 + i]
                              : sk[(2 * sseg + 1) * 256 + (511 - i)];
        }
        __syncthreads();
        c = 0;
        for (int x = tid; x < 4096; x += 512, ++c) sk[x] = tv[c];
        for (int j = 256; j > 0; j >>= 1) {
            __syncthreads();
            for (int t = tid; t < 2048; t += 512) {
                int seg = t >> 8, off = t & 255;
                int i = seg * 512 + (((off & ~(j - 1)) << 1) | (off & (j - 1)));
                u64 x = sk[i], y = sk[i + j];
                if (x < y) { sk[i] = y; sk[i + j] = x; }
            }
        }
    }

    // Phase B: tournament merge rounds (exact top-512 of each pair)
    for (int half = 4; half >= 1; half >>= 1) {
        const int nel = half * 512;
        __syncthreads();
        u64 va[4], vb[4];
        int cnt = 0;
        for (int e = tid; e < nel; e += 512, ++cnt) {
            int seg = e >> 9, i = e & 511;
            va[cnt] = sk[(seg * 2) * 512 + i];
            vb[cnt] = sk[(seg * 2 + 1) * 512 + 511 - i];
        }
        __syncthreads();
        cnt = 0;
        for (int e = tid; e < nel; e += 512, ++cnt)
            sk[e] = (va[cnt] > vb[cnt]) ? va[cnt] : vb[cnt];
        for (int j = 256; j > 0; j >>= 1) {
            __syncthreads();
            for (int c = tid; c < half * 256; c += 512) {
                int seg = c >> 8, off = c & 255;
                int i = seg * 512 + (((off & ~(j - 1)) << 1) | (off & (j - 1)));
                u64 x = sk[i], y = sk[i + j];
                if (x < y) { sk[i] = y; sk[i + j] = x; }
            }
        }
    }
    __syncthreads();

    u64* dst = g_cand + ((size_t)b * NCHUNK + blk) * KSEL;
    for (int i = tid; i < KSEL; i += 512) dst[i] = sk[i];
}

// ---------------- kernel 4: stage2 — tournament merge of 48 sorted 300-lists -------
__device__ __forceinline__ void t2_clean(u64* sk, int nseg, int tid) {
    for (int j = 256; j > 0; j >>= 1) {
        __syncthreads();
        for (int c = tid; c < nseg * 256; c += 1024) {
            int seg = c >> 8, off = c & 255;
            int i = seg * 512 + (((off & ~(j - 1)) << 1) | (off & (j - 1)));
            u64 x = sk[i], y = sk[i + j];
            if (x < y) { sk[i] = y; sk[i + j] = x; }
        }
    }
}

__global__ void __launch_bounds__(1024)
k_top2() {
    extern __shared__ u64 sk2[];   // 24 * 512 keys = 96 KB
    const int tid = threadIdx.x;
    const int b = blockIdx.x;
    const u64* src = g_cand + (size_t)b * NCAND;

    for (int e = tid; e < 24 * 512; e += 1024) {
        int seg = e >> 9, i = e & 511;
        u64 a = (i < KSEL) ? src[(seg * 2) * KSEL + i] : 0ull;
        int ri = 511 - i;
        u64 c = (ri < KSEL) ? src[(seg * 2 + 1) * KSEL + ri] : 0ull;
        sk2[e] = (a > c) ? a : c;
    }
    t2_clean(sk2, 24, tid);

    for (int nsegO = 12; nsegO >= 3; nsegO >>= 1) {
        const int nel = nsegO * 512;
        __syncthreads();
        u64 va[6], vb[6];
        int cnt = 0;
        for (int e = tid; e < nel; e += 1024, ++cnt) {
            int seg = e >> 9, i = e & 511;
            va[cnt] = sk2[(seg * 2) * 512 + i];
            vb[cnt] = sk2[(seg * 2 + 1) * 512 + 511 - i];
        }
        __syncthreads();
        cnt = 0;
        for (int e = tid; e < nel; e += 1024, ++cnt)
            sk2[e] = (va[cnt] > vb[cnt]) ? va[cnt] : vb[cnt];
        t2_clean(sk2, nsegO, tid);
    }

    for (int other = 1; other <= 2; ++other) {
        __syncthreads();
        u64 va0 = 0, vb0 = 0;
        if (tid < 512) {
            va0 = sk2[tid];
            vb0 = sk2[other * 512 + 511 - tid];
        }
        __syncthreads();
        if (tid < 512) sk2[tid] = (va0 > vb0) ? va0 : vb0;
        t2_clean(sk2, 1, tid);
    }
    __syncthreads();

    // emit + fused anchor grouping (slot order schedule-dependent; outputs slot-independent)
    if (tid < KSEL) {
        int sel = (int)(0xFFFFFFFFu - (u32)(sk2[tid] & 0xFFFFFFFFull));
        int n = b * KSEL + tid;
        g_sel[n] = sel;
        int a = sel % 9;
        int slot = atomicAdd(&g_cnt[a], 1);
        g_list[a * NSEL + slot] = n;
    }
}

// ---------------- kernel 5: anchor-grouped gather + 256x256 matvec (16 rows/block) ---
__global__ void __launch_bounds__(256)
k_post(const float* __restrict__ fm0, const float* __restrict__ fm1,
       const float* __restrict__ fm2, const float* __restrict__ fm3,
       const float* __restrict__ fm4, const float* __restrict__ w_post,
       const float* __restrict__ b_post, float* __restrict__ out) {
    __shared__ float xs[16 * 256];
    const int a = blockIdx.y;
    const int start = blockIdx.x * 16;
    const int cnt = g_cnt[a];
    if (start >= cnt) return;
    const int tid = threadIdx.x;
    const int nr = min(16, cnt - start);

#pragma unroll
    for (int r = 0; r < 16; ++r) xs[r * 256 + tid] = 0.f;

    int rows[16];
    for (int r = 0; r < nr; ++r) {
        int n = g_list[a * NSEL + start + r];
        rows[r] = n;
        int b = n / KSEL;
        int pos = g_sel[n] / 9;
        int m, hw, HW;
        if (pos < 16384)      { m = 0; hw = pos;         HW = 16384; }
        else if (pos < 20480) { m = 1; hw = pos - 16384; HW = 4096;  }
        else if (pos < 21504) { m = 2; hw = pos - 20480; HW = 1024;  }
        else if (pos < 21760) { m = 3; hw = pos - 21504; HW = 256;   }
        else                  { m = 4; hw = pos - 21760; HW = 64;    }
        const float* fm = (m == 0) ? fm0 : (m == 1) ? fm1 : (m == 2) ? fm2 : (m == 3) ? fm3 : fm4;
        xs[r * 256 + tid] = fm[((size_t)b * 256 + tid) * HW + hw];
    }
    __syncthreads();

    const float* W = w_post + (size_t)a * 65536;
    const float bb = b_post[a * 256 + tid];
    float acc[16];
#pragma unroll
    for (int r = 0; r < 16; ++r) acc[r] = bb;

#pragma unroll 2
    for (int d = 0; d < 256; ++d) {
        float w = W[d * 256 + tid];
#pragma unroll
        for (int r = 0; r < 16; ++r)
            acc[r] = fmaf(xs[r * 256 + d], w, acc[r]);
    }
    for (int r = 0; r < nr; ++r)
        out[(size_t)rows[r] * 256 + tid] = acc[r];
}

// ---------------- launch ----------------
extern "C" void kernel_launch(void* const* d_in, const int* in_sizes, int n_in,
                              void* d_out, int out_size) {
    const float* fm[5];
    for (int i = 0; i < 5; ++i) fm[i] = (const float*)d_in[i];
    const float* w_pre  = (const float*)d_in[5];
    const float* b_pre  = (const float*)d_in[6];
    const float* w_proj = (const float*)d_in[7];
    const float* b_proj = (const float*)d_in[8];
    const float* w_post = (const float*)d_in[9];
    const float* b_post = (const float*)d_in[10];
    float* out = (float*)d_out;

    const int convSmem = (2 * IB_FLOATS + 2 * WB_FLOATS) * 4;   // 81408 B
    const int top2Smem = 24 * 512 * 8;                          // 98304 B
    cudaFuncSetAttribute(k_conv, cudaFuncAttributeMaxDynamicSharedMemorySize, convSmem);
    cudaFuncSetAttribute(k_top2, cudaFuncAttributeMaxDynamicSharedMemorySize, top2Smem);

    k_wtrans<<<(NLOGIT + 1023) / 1024, 1024>>>(w_pre);

    {
        dim3 grid(341, BB, 2);   // tiles x batch x oc-half
        k_conv<<<grid, 256, convSmem>>>(fm[0], fm[1], fm[2], fm[3], fm[4], b_pre, w_proj);
    }
    {
        dim3 grid(NCHUNK, BB);
        k_top1<<<grid, 512>>>(b_proj);
    }
    k_top2<<<BB, 1024, top2Smem>>>();
    {
        dim3 grid((NSEL + 15) / 16, 9);
        k_post<<<grid, 256>>>(fm[0], fm[1], fm[2], fm[3], fm[4], w_post, b_post, out);
    }
}

// round 15
// speedup vs baseline: 1.2572x; 1.0039x over previous
#include <cuda_runtime.h>
#include <cstdint>

typedef unsigned long long u64;
typedef unsigned int u32;

// ---------------- problem constants ----------------
#define BB 8
#define CC 256
#define NPOS 21824              // per-image positions across 5 maps
#define NANCH 196416            // NPOS * 9
#define KSEL 300
#define NCHUNK 48               // stage1 chunks of 4096 per image
#define NCAND (NCHUNK * KSEL)   // 14400 candidates per image
#define NLOGIT (BB * NPOS * 9)  // 1571328
#define NSEL (BB * KSEL)        // 2400

__device__ __constant__ int c_mapS[5]   = {128, 64, 32, 16, 8};
__device__ __constant__ int c_mapOff[5] = {0, 16384, 20480, 21504, 21760};

// ---------------- device scratch ----------------
__device__ float g_wT[256 * 9 * 256];            // [ic][tap][oc]
__device__ float g_logits[(size_t)NLOGIT];       // fused proj output (2-way atomic, commutative)
__device__ u64   g_cand[(size_t)BB * NCAND];
__device__ u64   g_c2[(size_t)BB * 3 * 512];     // stage-2a outputs: 3 sorted 512-lists/image
__device__ int   g_sel[NSEL];
__device__ int   g_cnt[9];
__device__ int   g_list[9 * NSEL];

// ---------------- f32x2 helpers ----------------
__device__ __forceinline__ u64 dup2(float x) {
    u64 r; asm("mov.b64 %0,{%1,%1};" : "=l"(r) : "f"(x)); return r;
}
__device__ __forceinline__ void ffma2(u64 &c, u64 a, u64 b) {
    asm("fma.rn.f32x2 %0,%1,%2,%3;" : "=l"(c) : "l"(a), "l"(b), "l"(c));
}
__device__ __forceinline__ void fadd2(u64 &c, u64 a) {
    asm("add.rn.f32x2 %0,%1,%2;" : "=l"(c) : "l"(c), "l"(a));
}
__device__ __forceinline__ float2 unpack2(u64 v) {
    float2 f; asm("mov.b64 {%0,%1},%2;" : "=f"(f.x), "=f"(f.y) : "l"(v)); return f;
}

// ---------------- kernel 0: weight transpose + logit/counter zero (fused) ----------
__global__ void k_wtrans(const float* __restrict__ w_pre) {
    int i = blockIdx.x * 1024 + threadIdx.x;
    if (i < 256 * 9 * 256) {
        int oc = i & 255;
        int rest = i >> 8;
        int tap = rest % 9;
        int ic = rest / 9;
        g_wT[i] = w_pre[(oc * 256 + ic) * 9 + tap];
    }
    if (i < NLOGIT) g_logits[i] = 0.f;
    if (i < 9) g_cnt[i] = 0;
}

// ---------------- kernel 1: conv3x3 + bias + relu + fused 1x1 proj (R9 winner) -------
#define IB_FLOATS 960            // 8*10*12
#define WB_FLOATS 9216           // 8*9*128
#define W_CHUNK_BYTES 73728      // 8*9*256*4

#define LOADROW(dst, rr) { \
    float2 a_ = *(const float2*)(ib + (rr)*12); \
    float2 b_ = *(const float2*)(ib + (rr)*12 + 2); \
    dst[0] = dup2(a_.x); dst[1] = dup2(a_.y); \
    dst[2] = dup2(b_.x); dst[3] = dup2(b_.y); }

#define TAPROW(dy, top, bot) { \
    _Pragma("unroll") \
    for (int dx = 0; dx < 3; ++dx) { \
        const ulonglong2* wp = (const ulonglong2*)(wb + ((dy)*3 + dx) * 128); \
        ulonglong2 wA = wp[0]; \
        ulonglong2 wB = wp[1]; \
        ffma2(ch[0][0], top[dx],   wA.x); ffma2(ch[0][1], top[dx],   wA.y); \
        ffma2(ch[0][2], top[dx],   wB.x); ffma2(ch[0][3], top[dx],   wB.y); \
        ffma2(ch[1][0], top[dx+1], wA.x); ffma2(ch[1][1], top[dx+1], wA.y); \
        ffma2(ch[1][2], top[dx+1], wB.x); ffma2(ch[1][3], top[dx+1], wB.y); \
        ffma2(ch[2][0], bot[dx],   wA.x); ffma2(ch[2][1], bot[dx],   wA.y); \
        ffma2(ch[2][2], bot[dx],   wB.x); ffma2(ch[2][3], bot[dx],   wB.y); \
        ffma2(ch[3][0], bot[dx+1], wA.x); ffma2(ch[3][1], bot[dx+1], wA.y); \
        ffma2(ch[3][2], bot[dx+1], wB.x); ffma2(ch[3][3], bot[dx+1], wB.y); \
    } }

__global__ void __launch_bounds__(256, 2)
k_conv(const float* __restrict__ fm0, const float* __restrict__ fm1,
       const float* __restrict__ fm2, const float* __restrict__ fm3,
       const float* __restrict__ fm4, const float* __restrict__ b_pre,
       const float* __restrict__ w_proj) {
    extern __shared__ float sm[];
    float* ibuf[2] = {sm, sm + IB_FLOATS};
    float* wbuf[2] = {sm + 2 * IB_FLOATS, sm + 2 * IB_FLOATS + WB_FLOATS};
    const u32 smb = (u32)__cvta_generic_to_shared(sm);
    const u32 ibs[2] = {smb, smb + IB_FLOATS * 4};
    const u32 wbs[2] = {smb + 2 * IB_FLOATS * 4, smb + 2 * IB_FLOATS * 4 + WB_FLOATS * 4};

    const int tid = threadIdx.x;
    const int b = blockIdx.y;
    const int zh = blockIdx.z;

    int bx = blockIdx.x, m, tile;
    if (bx < 256)      { m = 0; tile = bx; }
    else if (bx < 320) { m = 1; tile = bx - 256; }
    else if (bx < 336) { m = 2; tile = bx - 320; }
    else if (bx < 340) { m = 3; tile = bx - 336; }
    else               { m = 4; tile = bx - 340; }
    const int s = c_mapS[m];
    const int HW = s * s;
    const int posOff = c_mapOff[m];
    const float* fm = (m == 0) ? fm0 : (m == 1) ? fm1 : (m == 2) ? fm2 : (m == 3) ? fm3 : fm4;

    const int tilesX = s >> 3;
    const int ty0 = (tile / tilesX) << 3;
    const int tx0 = (tile % tilesX) << 3;

    const int pg = tid & 15;
    const int og = tid >> 4;
    const int py = (pg >> 2) << 1;
    const int px = (pg & 3) << 1;

    const char* fb = (const char*)(fm + (size_t)b * 256 * HW);

    bool in_act[4];
    u32  in_so[4], in_go[4], in_sz[4];
#pragma unroll
    for (int k = 0; k < 4; ++k) {
        int idx = tid + (k << 8);
        in_act[k] = (idx < 800);
        int ii = in_act[k] ? idx : 0;
        int ic = ii / 100;
        int rem = ii - ic * 100;
        int r = rem / 10;
        int c = rem - 10 * r;
        int gy = ty0 - 1 + r, gx = tx0 - 1 + c;
        bool ok = (gy >= 0) && (gy < s) && (gx >= 0) && (gx < s);
        in_so[k] = (u32)(((ic * 10 + r) * 12 + c) * 4);
        in_go[k] = ok ? (u32)((ic * HW + gy * s + gx) * 4) : 0u;
        in_sz[k] = ok ? 4u : 0u;
    }
    u32 w_so[9], w_go[9];
#pragma unroll
    for (int k = 0; k < 9; ++k) {
        int i = tid + (k << 8);
        int icL = i / 288;
        int rem = i - icL * 288;
        int tap = rem >> 5;
        int q = rem & 31;
        w_so[k] = (u32)(i * 16);
        w_go[k] = (u32)(((((icL * 9 + tap) << 6) + (zh << 5) + q)) * 16);
    }
    const char* wtb = (const char*)g_wT;

    u64 acc[4][4];
#pragma unroll
    for (int p = 0; p < 4; ++p)
#pragma unroll
        for (int j = 0; j < 4; ++j) acc[p][j] = 0ull;

    {
#pragma unroll
        for (int k = 0; k < 4; ++k) if (in_act[k])
            asm volatile("cp.async.ca.shared.global [%0], [%1], 4, %2;"
                         :: "r"(ibs[0] + in_so[k]), "l"(fb + in_go[k]), "r"(in_sz[k]) : "memory");
#pragma unroll
        for (int k = 0; k < 9; ++k)
            asm volatile("cp.async.cg.shared.global [%0], [%1], 16;"
                         :: "r"(wbs[0] + w_so[k]), "l"(wtb + w_go[k]) : "memory");
        asm volatile("cp.async.commit_group;" ::: "memory");
    }

    const u32 inStride = (u32)(8 * HW * 4);

    for (int cc = 0; cc < 32; ++cc) {
        const int cur = cc & 1;
        asm volatile("cp.async.wait_group 0;" ::: "memory");
        __syncthreads();
        if (cc < 31) {
            const char* f = fb + (size_t)(cc + 1) * inStride;
            const char* w = wtb + (size_t)(cc + 1) * W_CHUNK_BYTES;
            const u32 ibS = ibs[cur ^ 1], wbS = wbs[cur ^ 1];
#pragma unroll
            for (int k = 0; k < 4; ++k) if (in_act[k])
                asm volatile("cp.async.ca.shared.global [%0], [%1], 4, %2;"
                             :: "r"(ibS + in_so[k]), "l"(f + in_go[k]), "r"(in_sz[k]) : "memory");
#pragma unroll
            for (int k = 0; k < 9; ++k)
                asm volatile("cp.async.cg.shared.global [%0], [%1], 16;"
                             :: "r"(wbS + w_so[k]), "l"(w + w_go[k]) : "memory");
            asm volatile("cp.async.commit_group;" ::: "memory");
        }

        u64 ch[4][4];
#pragma unroll
        for (int p = 0; p < 4; ++p)
#pragma unroll
            for (int j = 0; j < 4; ++j) ch[p][j] = 0ull;

        const float* ibase = ibuf[cur] + py * 12 + px;
        const float* wbase2 = wbuf[cur] + og * 8;
#pragma unroll
        for (int ic = 0; ic < 8; ++ic) {
            const float* ib = ibase + ic * 120;
            const float* wb = wbase2 + ic * 1152;
            u64 rA[4], rB[4];
            LOADROW(rA, 0);
            LOADROW(rB, 1);
            TAPROW(0, rA, rB);
            LOADROW(rA, 2);
            TAPROW(1, rB, rA);
            LOADROW(rB, 3);
            TAPROW(2, rA, rB);
        }
#pragma unroll
        for (int p = 0; p < 4; ++p)
#pragma unroll
            for (int j = 0; j < 4; ++j) fadd2(acc[p][j], ch[p][j]);
    }

    // ---- fused epilogue: bias + relu + 1x1 proj partials ----
    float part[4][9];
#pragma unroll
    for (int p = 0; p < 4; ++p)
#pragma unroll
        for (int a = 0; a < 9; ++a) part[p][a] = 0.f;

#pragma unroll
    for (int j = 0; j < 4; ++j) {
        const int oc = zh * 128 + og * 8 + 2 * j;
        const float b0 = b_pre[oc], b1 = b_pre[oc + 1];
#pragma unroll
        for (int p = 0; p < 4; ++p) {
            float2 v = unpack2(acc[p][j]);
            float r0 = fmaxf(v.x + b0, 0.f);
            float r1 = fmaxf(v.y + b1, 0.f);
#pragma unroll
            for (int a = 0; a < 9; ++a) {
                float t = part[p][a];
                t = fmaf(r0, w_proj[a * 256 + oc], t);
                t = fmaf(r1, w_proj[a * 256 + oc + 1], t);
                part[p][a] = t;
            }
        }
    }

    float* red = wbuf[0];
#pragma unroll
    for (int p = 0; p < 4; ++p) {
        int pl = (py + (p >> 1)) * 8 + (px + (p & 1));
#pragma unroll
        for (int a = 0; a < 9; ++a)
            red[(og * 64 + pl) * 9 + a] = part[p][a];
    }
    __syncthreads();

    for (int item = tid; item < 576; item += 256) {
        int pl = item / 9;
        int a = item - 9 * pl;
        float v = 0.f;
#pragma unroll
        for (int o = 0; o < 16; ++o)
            v += red[(o * 64 + pl) * 9 + a];
        int gy = ty0 + (pl >> 3);
        int gx = tx0 + (pl & 7);
        int pos = posOff + gy * s + gx;
        atomicAdd(&g_logits[((size_t)b * NPOS + pos) * 9 + a], v);
    }
}

// ---------------- warp-level bitonic sort (descending) of 256 keys, 8/lane ----------
__device__ __forceinline__ void warp_sort256_desc(u64 v[8], int lane) {
#pragma unroll
    for (int k = 2; k <= 256; k <<= 1) {
#pragma unroll
        for (int j = k >> 1; j > 0; j >>= 1) {
            if (j >= 32) {
                const int jr = j >> 5;
#pragma unroll
                for (int r = 0; r < 8; ++r) {
                    if ((r & jr) == 0) {
                        const int r2 = r | jr;
                        const bool wantmax = (((r * 32) & k) == 0);
                        u64 a = v[r], bq = v[r2];
                        u64 mx = a > bq ? a : bq;
                        u64 mn = a > bq ? bq : a;
                        v[r]  = wantmax ? mx : mn;
                        v[r2] = wantmax ? mn : mx;
                    }
                }
            } else {
#pragma unroll
                for (int r = 0; r < 8; ++r) {
                    u64 p = __shfl_xor_sync(0xFFFFFFFFu, v[r], j);
                    const int eak = (k >= 32) ? ((r * 32) & k) : (lane & k);
                    const bool wantmax = (eak == 0);
                    const bool is_low = ((lane & j) == 0);
                    const bool takemax = (is_low == wantmax);
                    u64 mx = v[r] > p ? v[r] : p;
                    u64 mn = v[r] > p ? p : v[r];
                    v[r] = takemax ? mx : mn;
                }
            }
        }
    }
}

// ---------------- kernel 3: stage1 — keys inline + warp sort + tournament top-300 ----
__global__ void __launch_bounds__(512)
k_top1(const float* __restrict__ b_proj) {
    __shared__ u64 sk[4096];
    const int tid = threadIdx.x;
    const int lane = tid & 31;
    const int w = tid >> 5;
    const int blk = blockIdx.x;
    const int b = blockIdx.y;
    const float* lg = g_logits + (size_t)b * NPOS * 9;

    u64 v[8];
#pragma unroll
    for (int r = 0; r < 8; ++r) {
        int aidx = blk * 4096 + w * 256 + r * 32 + lane;
        u64 key = 0ull;
        if (aidx < NANCH) {
            int p = aidx / 9;
            int a = aidx - 9 * p;
            float logit = lg[aidx] + b_proj[a];
            float prob = 1.0f / (1.0f + expf(-logit));
            u32 pb = __float_as_uint(prob);
            key = ((u64)pb << 32) | (u64)(0xFFFFFFFFu - (u32)aidx);
        }
        v[r] = key;
    }
    warp_sort256_desc(v, lane);
#pragma unroll
    for (int r = 0; r < 8; ++r)
        sk[w * 256 + r * 32 + lane] = v[r];
    __syncthreads();

    // Full merge 16x256 -> 8x512
    {
        u64 tv[8];
        int c = 0;
        for (int x = tid; x < 4096; x += 512, ++c) {
            int sseg = x >> 9, i = x & 511;
            tv[c] = (i < 256) ? sk[(2 * sseg) * 256 + i]
                              : sk[(2 * sseg + 1) * 256 + (511 - i)];
        }
        __syncthreads();
        c = 0;
        for (int x = tid; x < 4096; x += 512, ++c) sk[x] = tv[c];
        for (int j = 256; j > 0; j >>= 1) {
            __syncthreads();
            for (int t = tid; t < 2048; t += 512) {
                int seg = t >> 8, off = t & 255;
                int i = seg * 512 + (((off & ~(j - 1)) << 1) | (off & (j - 1)));
                u64 x = sk[i], y = sk[i + j];
                if (x < y) { sk[i] = y; sk[i + j] = x; }
            }
        }
    }

    // Phase B: tournament merge rounds
    for (int half = 4; half >= 1; half >>= 1) {
        const int nel = half * 512;
        __syncthreads();
        u64 va[4], vb[4];
        int cnt = 0;
        for (int e = tid; e < nel; e += 512, ++cnt) {
            int seg = e >> 9, i = e & 511;
            va[cnt] = sk[(seg * 2) * 512 + i];
            vb[cnt] = sk[(seg * 2 + 1) * 512 + 511 - i];
        }
        __syncthreads();
        cnt = 0;
        for (int e = tid; e < nel; e += 512, ++cnt)
            sk[e] = (va[cnt] > vb[cnt]) ? va[cnt] : vb[cnt];
        for (int j = 256; j > 0; j >>= 1) {
            __syncthreads();
            for (int c = tid; c < half * 256; c += 512) {
                int seg = c >> 8, off = c & 255;
                int i = seg * 512 + (((off & ~(j - 1)) << 1) | (off & (j - 1)));
                u64 x = sk[i], y = sk[i + j];
                if (x < y) { sk[i] = y; sk[i + j] = x; }
            }
        }
    }
    __syncthreads();

    u64* dst = g_cand + ((size_t)b * NCHUNK + blk) * KSEL;
    for (int i = tid; i < KSEL; i += 512) dst[i] = sk[i];
}

// ---------------- kernel 4a: stage2a — each block merges 16 sorted lists -> top-512 --
// Exact by induction on the bitonic half-cleaner (each pair-merge keeps exact
// top-512 of the pair; 512 >= 300 bounds any group's contribution to global top-300).
__device__ __forceinline__ void t2_clean(u64* sk, int nseg, int tid, int nthr) {
    for (int j = 256; j > 0; j >>= 1) {
        __syncthreads();
        for (int c = tid; c < nseg * 256; c += nthr) {
            int seg = c >> 8, off = c & 255;
            int i = seg * 512 + (((off & ~(j - 1)) << 1) | (off & (j - 1)));
            u64 x = sk[i], y = sk[i + j];
            if (x < y) { sk[i] = y; sk[i + j] = x; }
        }
    }
}

__global__ void __launch_bounds__(1024)
k_top2a() {
    extern __shared__ u64 sk2[];   // 8 * 512 keys = 32 KB
    const int tid = threadIdx.x;
    const int grp = blockIdx.x;    // 0..2: lists [grp*16, grp*16+16)
    const int b = blockIdx.y;
    const u64* src = g_cand + (size_t)b * NCAND + (size_t)grp * 16 * KSEL;

    // Round 1: 16 global lists -> 8 smem segments
    for (int e = tid; e < 8 * 512; e += 1024) {
        int seg = e >> 9, i = e & 511;
        u64 a = (i < KSEL) ? src[(seg * 2) * KSEL + i] : 0ull;
        int ri = 511 - i;
        u64 c = (ri < KSEL) ? src[(seg * 2 + 1) * KSEL + ri] : 0ull;
        sk2[e] = (a > c) ? a : c;
    }
    t2_clean(sk2, 8, tid, 1024);

    // Rounds 8->4->2->1
    for (int nsegO = 4; nsegO >= 1; nsegO >>= 1) {
        const int nel = nsegO * 512;
        __syncthreads();
        u64 va[2], vb[2];
        int cnt = 0;
        for (int e = tid; e < nel; e += 1024, ++cnt) {
            int seg = e >> 9, i = e & 511;
            va[cnt] = sk2[(seg * 2) * 512 + i];
            vb[cnt] = sk2[(seg * 2 + 1) * 512 + 511 - i];
        }
        __syncthreads();
        cnt = 0;
        for (int e = tid; e < nel; e += 1024, ++cnt)
            sk2[e] = (va[cnt] > vb[cnt]) ? va[cnt] : vb[cnt];
        t2_clean(sk2, nsegO, tid, 1024);
    }
    __syncthreads();

    u64* dst = g_c2 + ((size_t)b * 3 + grp) * 512;
    for (int i = tid; i < 512; i += 1024) dst[i] = sk2[i];
}

// ---------------- kernel 4b: stage2b — merge 3 sorted 512-lists, emit + group -------
__global__ void __launch_bounds__(512)
k_top2b() {
    __shared__ u64 sk[512];
    const int tid = threadIdx.x;
    const int b = blockIdx.x;
    const u64* src = g_c2 + (size_t)b * 3 * 512;

    sk[tid] = src[tid];
    for (int other = 1; other <= 2; ++other) {
        __syncthreads();
        u64 va = sk[tid];
        u64 vb = src[other * 512 + 511 - tid];
        __syncthreads();
        sk[tid] = (va > vb) ? va : vb;
        for (int j = 256; j > 0; j >>= 1) {
            __syncthreads();
            if (tid < 256) {
                int i = ((tid & ~(j - 1)) << 1) | (tid & (j - 1));
                u64 x = sk[i], y = sk[i + j];
                if (x < y) { sk[i] = y; sk[i + j] = x; }
            }
        }
    }
    __syncthreads();

    // emit + fused anchor grouping (slot order schedule-dependent; outputs slot-independent)
    if (tid < KSEL) {
        int sel = (int)(0xFFFFFFFFu - (u32)(sk[tid] & 0xFFFFFFFFull));
        int n = b * KSEL + tid;
        g_sel[n] = sel;
        int a = sel % 9;
        int slot = atomicAdd(&g_cnt[a], 1);
        g_list[a * NSEL + slot] = n;
    }
}

// ---------------- kernel 5: anchor-grouped gather + 256x256 matvec (16 rows/block) ---
__global__ void __launch_bounds__(256)
k_post(const float* __restrict__ fm0, const float* __restrict__ fm1,
       const float* __restrict__ fm2, const float* __restrict__ fm3,
       const float* __restrict__ fm4, const float* __restrict__ w_post,
       const float* __restrict__ b_post, float* __restrict__ out) {
    __shared__ float xs[16 * 256];
    const int a = blockIdx.y;
    const int start = blockIdx.x * 16;
    const int cnt = g_cnt[a];
    if (start >= cnt) return;
    const int tid = threadIdx.x;
    const int nr = min(16, cnt - start);

#pragma unroll
    for (int r = 0; r < 16; ++r) xs[r * 256 + tid] = 0.f;

    int rows[16];
    for (int r = 0; r < nr; ++r) {
        int n = g_list[a * NSEL + start + r];
        rows[r] = n;
        int b = n / KSEL;
        int pos = g_sel[n] / 9;
        int m, hw, HW;
        if (pos < 16384)      { m = 0; hw = pos;         HW = 16384; }
        else if (pos < 20480) { m = 1; hw = pos - 16384; HW = 4096;  }
        else if (pos < 21504) { m = 2; hw = pos - 20480; HW = 1024;  }
        else if (pos < 21760) { m = 3; hw = pos - 21504; HW = 256;   }
        else                  { m = 4; hw = pos - 21760; HW = 64;    }
        const float* fm = (m == 0) ? fm0 : (m == 1) ? fm1 : (m == 2) ? fm2 : (m == 3) ? fm3 : fm4;
        xs[r * 256 + tid] = fm[((size_t)b * 256 + tid) * HW + hw];
    }
    __syncthreads();

    const float* W = w_post + (size_t)a * 65536;
    const float bb = b_post[a * 256 + tid];
    float acc[16];
#pragma unroll
    for (int r = 0; r < 16; ++r) acc[r] = bb;

#pragma unroll 2
    for (int d = 0; d < 256; ++d) {
        float w = W[d * 256 + tid];
#pragma unroll
        for (int r = 0; r < 16; ++r)
            acc[r] = fmaf(xs[r * 256 + d], w, acc[r]);
    }
    for (int r = 0; r < nr; ++r)
        out[(size_t)rows[r] * 256 + tid] = acc[r];
}

// ---------------- launch ----------------
extern "C" void kernel_launch(void* const* d_in, const int* in_sizes, int n_in,
                              void* d_out, int out_size) {
    const float* fm[5];
    for (int i = 0; i < 5; ++i) fm[i] = (const float*)d_in[i];
    const float* w_pre  = (const float*)d_in[5];
    const float* b_pre  = (const float*)d_in[6];
    const float* w_proj = (const float*)d_in[7];
    const float* b_proj = (const float*)d_in[8];
    const float* w_post = (const float*)d_in[9];
    const float* b_post = (const float*)d_in[10];
    float* out = (float*)d_out;

    const int convSmem = (2 * IB_FLOATS + 2 * WB_FLOATS) * 4;   // 81408 B
    const int top2aSmem = 8 * 512 * 8;                          // 32768 B
    cudaFuncSetAttribute(k_conv, cudaFuncAttributeMaxDynamicSharedMemorySize, convSmem);
    cudaFuncSetAttribute(k_top2a, cudaFuncAttributeMaxDynamicSharedMemorySize, top2aSmem);

    k_wtrans<<<(NLOGIT + 1023) / 1024, 1024>>>(w_pre);

    {
        dim3 grid(341, BB, 2);   // tiles x batch x oc-half
        k_conv<<<grid, 256, convSmem>>>(fm[0], fm[1], fm[2], fm[3], fm[4], b_pre, w_proj);
    }
    {
        dim3 grid(NCHUNK, BB);
        k_top1<<<grid, 512>>>(b_proj);
    }
    {
        dim3 grid(3, BB);
        k_top2a<<<grid, 1024, top2aSmem>>>();
    }
    k_top2b<<<BB, 512>>>();
    {
        dim3 grid((NSEL + 15) / 16, 9);
        k_post<<<grid, 256>>>(fm[0], fm[1], fm[2], fm[3], fm[4], w_post, b_post, out);
    }
}